// round 10
// baseline (speedup 1.0000x reference)
#include <cuda_runtime.h>
#include <math.h>
#include <float.h>

#define N_PTS 4096
#define BATCH 4
#define C_IN  64
#define C_OUT 128
#define KNN   20
#define C_BOT 16
#define EPSBN 1e-5f

// ---------------- scratch (device globals; no allocation) ----------------
__device__ float g_sq[BATCH * N_PTS];                       // 64 KB
__device__ float g_hb[BATCH * N_PTS * C_BOT];               // 1 MB, [B*N,16]
__device__ float g_d2[(size_t)BATCH * N_PTS * N_PTS];       // 256 MiB
__device__ float g_min16[(size_t)BATCH * N_PTS * 256];      // 16 MiB group minima
__device__ int   g_idx[BATCH * N_PTS * KNN];                // 1.3 MB
__device__ float g_allf[(size_t)BATCH * N_PTS * 96];        // 25 MB, [B*N,96]
__device__ float g_Wt[160 * 128];                           // folded [k][o]
__device__ float g_bias[256];                               // tDec[128], tRes[128]

// ---------------- f32x2 helpers (Blackwell packed FMA path) -----------------
__device__ __forceinline__ unsigned long long pk2(float x, float y) {
    unsigned long long r;
    asm("mov.b64 %0, {%1,%2};" : "=l"(r) : "f"(x), "f"(y));
    return r;
}
__device__ __forceinline__ void upk2(unsigned long long v, float& x, float& y) {
    asm("mov.b64 {%0,%1}, %2;" : "=f"(x), "=f"(y) : "l"(v));
}
__device__ __forceinline__ unsigned long long fma2(unsigned long long a,
                                                   unsigned long long b,
                                                   unsigned long long c) {
    unsigned long long d;
    asm("fma.rn.f32x2 %0, %1, %2, %3;" : "=l"(d) : "l"(a), "l"(b), "l"(c));
    return d;
}
__device__ __forceinline__ unsigned okey(float f) {
    unsigned u = __float_as_uint(f);
    return u ^ (unsigned)(((int)u >> 31) | 0x80000000);
}
__device__ __forceinline__ float unokey(unsigned k) {
    return __uint_as_float((k & 0x80000000u) ? (k ^ 0x80000000u) : ~k);
}

// ---------------- K1: sq norms + bottleneck conv (BN+ReLU), hb transposed ----
__global__ void k_prep(const float* __restrict__ x,
                       const float* __restrict__ Wb, const float* __restrict__ gb,
                       const float* __restrict__ bb, const float* __restrict__ mb,
                       const float* __restrict__ vb)
{
    __shared__ float sW[C_BOT][C_IN];
    __shared__ float sS[C_BOT], sT[C_BOT];
    int tid = threadIdx.x;
    if (tid < C_BOT) {
        float s = gb[tid] * rsqrtf(vb[tid] + EPSBN);
        sS[tid] = s;
        sT[tid] = bb[tid] - mb[tid] * s;
    }
    for (int e = tid; e < C_BOT * C_IN; e += blockDim.x)
        sW[e >> 6][e & 63] = Wb[e];
    __syncthreads();

    int g = blockIdx.x * blockDim.x + tid;      // 0 .. BATCH*N_PTS-1
    if (g >= BATCH * N_PTS) return;
    int b = g >> 12, n = g & (N_PTS - 1);
    const float* xp = x + (size_t)b * C_IN * N_PTS + n;

    float xc[C_IN];
    float sq = 0.f;
#pragma unroll
    for (int c = 0; c < C_IN; c++) {
        float v = xp[(size_t)c * N_PTS];
        xc[c] = v;
        sq += v * v;                 // same ascending-c order as GEMM dot
    }
    g_sq[g] = sq;

#pragma unroll
    for (int o = 0; o < C_BOT; o++) {
        float acc = 0.f;
#pragma unroll
        for (int c = 0; c < C_IN; c++) acc += sW[o][c] * xc[c];
        float h = acc * sS[o] + sT[o];
        g_hb[(size_t)g * C_BOT + o] = fmaxf(h, 0.f);
    }
}

// ------- K2: pairwise distances, 128x128 tile, 8x8/thread f32x2 + group mins
__global__ void __launch_bounds__(256) k_dist(const float* __restrict__ x)
{
    extern __shared__ float smd[];
    float* As  = smd;                  // 64*128
    float* Bs  = As + 64 * 128;        // 64*128
    float* sqA = Bs + 64 * 128;        // 128
    float* sqB = sqA + 128;            // 128

    int b  = blockIdx.z;
    int bi = blockIdx.y;
    int bj = blockIdx.x;
    int tid = threadIdx.x;
    const float* xb = x + (size_t)b * C_IN * N_PTS;

    for (int e = tid; e < 64 * 32; e += 256) {
        int k = e >> 5, i = e & 31;
        ((float4*)As)[k * 32 + i] =
            *(const float4*)&xb[(size_t)k * N_PTS + bi * 128 + i * 4];
        ((float4*)Bs)[k * 32 + i] =
            *(const float4*)&xb[(size_t)k * N_PTS + bj * 128 + i * 4];
    }
    if (tid < 128)      sqA[tid]       = g_sq[b * N_PTS + bi * 128 + tid];
    else                sqB[tid - 128] = g_sq[b * N_PTS + bj * 128 + (tid - 128)];
    __syncthreads();

    int tx = tid & 15, ty = tid >> 4;
    const float4* As4 = (const float4*)As;
    const unsigned long long* Bs8 = (const unsigned long long*)Bs;

    unsigned long long acc2[8][4];
#pragma unroll
    for (int i = 0; i < 8; i++)
#pragma unroll
        for (int j = 0; j < 4; j++) acc2[i][j] = 0ULL;

#pragma unroll 2
    for (int k = 0; k < 64; k++) {
        float4 a0 = As4[k * 32 + ty * 2];
        float4 a1 = As4[k * 32 + ty * 2 + 1];
        unsigned long long B0 = Bs8[k * 64 + tx * 4 + 0];
        unsigned long long B1 = Bs8[k * 64 + tx * 4 + 1];
        unsigned long long B2 = Bs8[k * 64 + tx * 4 + 2];
        unsigned long long B3 = Bs8[k * 64 + tx * 4 + 3];
        unsigned long long A[8];
        A[0] = pk2(a0.x, a0.x); A[1] = pk2(a0.y, a0.y);
        A[2] = pk2(a0.z, a0.z); A[3] = pk2(a0.w, a0.w);
        A[4] = pk2(a1.x, a1.x); A[5] = pk2(a1.y, a1.y);
        A[6] = pk2(a1.z, a1.z); A[7] = pk2(a1.w, a1.w);
#pragma unroll
        for (int i = 0; i < 8; i++) {
            acc2[i][0] = fma2(A[i], B0, acc2[i][0]);
            acc2[i][1] = fma2(A[i], B1, acc2[i][1]);
            acc2[i][2] = fma2(A[i], B2, acc2[i][2]);
            acc2[i][3] = fma2(A[i], B3, acc2[i][3]);
        }
    }

#pragma unroll
    for (int ri = 0; ri < 8; ri++) {
        int r = ty * 8 + ri;
        float sr = sqA[r];
        float c0, c1;
        float4 v0, v1;
        upk2(acc2[ri][0], c0, c1);
        v0.x = sr + sqB[tx * 8 + 0] - 2.f * c0;
        v0.y = sr + sqB[tx * 8 + 1] - 2.f * c1;
        upk2(acc2[ri][1], c0, c1);
        v0.z = sr + sqB[tx * 8 + 2] - 2.f * c0;
        v0.w = sr + sqB[tx * 8 + 3] - 2.f * c1;
        upk2(acc2[ri][2], c0, c1);
        v1.x = sr + sqB[tx * 8 + 4] - 2.f * c0;
        v1.y = sr + sqB[tx * 8 + 5] - 2.f * c1;
        upk2(acc2[ri][3], c0, c1);
        v1.z = sr + sqB[tx * 8 + 6] - 2.f * c0;
        v1.w = sr + sqB[tx * 8 + 7] - 2.f * c1;
        float* dp = g_d2 + ((size_t)(b * N_PTS + bi * 128 + r)) * N_PTS +
                    bj * 128 + tx * 8;
        *(float4*)dp = v0;
        *(float4*)(dp + 4) = v1;

        // per-row 16-element group minimum (2 adjacent tx threads per group)
        float mn = fminf(fminf(fminf(v0.x, v0.y), fminf(v0.z, v0.w)),
                         fminf(fminf(v1.x, v1.y), fminf(v1.z, v1.w)));
        float mo = __shfl_xor_sync(0xffffffffu, mn, 1);
        mn = fminf(mn, mo);
        if ((tx & 1) == 0)
            g_min16[((size_t)(b * N_PTS + bi * 128 + r)) * 256 + bj * 8 +
                    (tx >> 1)] = mn;
    }
}

// -------- K3: hierarchical top-K via group minima ---------------------------
__global__ void __launch_bounds__(256) k_topk()
{
    int lane = threadIdx.x & 31, w = threadIdx.x >> 5;
    int row = blockIdx.x * 8 + w;              // b*N + n
    const float* dp = g_d2 + (size_t)row * N_PTS;
    const float* gm = g_min16 + (size_t)row * 256;

    // ---- init: elements 0..31 (groups 0,1), bitonic sort ascending ----
    unsigned u0 = okey(dp[lane]);
    unsigned long long p = ((unsigned long long)u0 << 32) | (unsigned)lane;
#pragma unroll
    for (int k2 = 2; k2 <= 32; k2 <<= 1) {
#pragma unroll
        for (int j = k2 >> 1; j > 0; j >>= 1) {
            unsigned long long q = __shfl_xor_sync(0xffffffffu, p, j);
            bool up = ((lane & k2) == 0);
            bool lower = ((lane & j) == 0);
            bool takeMin = (up == lower);
            bool qs = q < p;
            p = (takeMin == qs) ? q : p;
        }
    }
    unsigned long long thr = __shfl_sync(0xffffffffu, p, KNN - 1);
    float thrF = unokey((unsigned)(thr >> 32));

    // ---- scan 256 group minima; fetch qualifying groups only ----
#pragma unroll 1
    for (int c = 0; c < 8; c++) {
        float gmin = gm[c * 32 + lane];
        bool cand = (gmin <= thrF) && (c * 32 + lane >= 2);   // groups 0,1 done
        unsigned hit = __ballot_sync(0xffffffffu, cand);
        while (hit) {
            int src = __ffs(hit) - 1;
            hit &= hit - 1;
            float gsrc = __shfl_sync(0xffffffffu, gmin, src);
            if (gsrc > thrF) continue;          // threshold tightened since
            int g = c * 32 + src;
            float v = dp[g * 16 + (lane & 15)];
            unsigned uk = okey(v);
            unsigned h2 = __ballot_sync(0xffffffffu, (lane < 16) && (v <= thrF));
            while (h2) {
                int s2 = __ffs(h2) - 1;
                h2 &= h2 - 1;
                unsigned ks = __shfl_sync(0xffffffffu, uk, s2);
                unsigned long long pn = ((unsigned long long)ks << 32) |
                                        (unsigned)(g * 16 + s2);
                if (pn < thr) {                 // exact final decision
                    unsigned pm = __ballot_sync(0xffffffffu, p < pn);
                    int pos = __popc(pm);
                    unsigned long long up = __shfl_up_sync(0xffffffffu, p, 1);
                    if (lane == pos)      p = pn;
                    else if (lane > pos)  p = up;
                    thr = __shfl_sync(0xffffffffu, p, KNN - 1);
                    thrF = unokey((unsigned)(thr >> 32));
                }
            }
        }
    }

    if (lane < KNN)
        g_idx[row * KNN + lane] = (int)(p & 0xFFFFFFFFULL);
}

// -------- K4a: fold decoder+residual weights (BN scale) into g_Wt -----------
__global__ void k_fold(const float* __restrict__ Wdec, const float* __restrict__ gdec,
                       const float* __restrict__ bdec, const float* __restrict__ mdec,
                       const float* __restrict__ vdec,
                       const float* __restrict__ Wres, const float* __restrict__ gres,
                       const float* __restrict__ bres, const float* __restrict__ mres,
                       const float* __restrict__ vres)
{
    int tid = blockIdx.x * blockDim.x + threadIdx.x;
    for (int e = tid; e < 160 * 128; e += gridDim.x * blockDim.x) {
        int k = e >> 7, o = e & 127;
        float wv;
        if (k < 96) wv = Wdec[o * 96 + k] * (gdec[o] * rsqrtf(vdec[o] + EPSBN));
        else        wv = Wres[o * 64 + (k - 96)] * (gres[o] * rsqrtf(vres[o] + EPSBN));
        g_Wt[e] = wv;
    }
    if (tid < 128) {
        float sd = gdec[tid] * rsqrtf(vdec[tid] + EPSBN);
        g_bias[tid] = bdec[tid] - mdec[tid] * sd;
        float sr = gres[tid] * rsqrtf(vres[tid] + EPSBN);
        g_bias[128 + tid] = bres[tid] - mres[tid] * sr;
    }
}

// -------- K4b: GCN branches + gmax, one warp per point ----------------------
__global__ void __launch_bounds__(256) k_gcn(
    const float* __restrict__ Wg1, const float* __restrict__ gg1,
    const float* __restrict__ bg1, const float* __restrict__ mg1,
    const float* __restrict__ vg1,
    const float* __restrict__ Wg2, const float* __restrict__ gg2,
    const float* __restrict__ bg2, const float* __restrict__ mg2,
    const float* __restrict__ vg2)
{
    __shared__ float sW1[32 * 33], sW2[32 * 33];
    __shared__ float sS1[32], sS2[32], t1[32], t2[32];
    __shared__ float sNb[8][KNN * 16];
    __shared__ float sCtr[8][16];

    int tid = threadIdx.x, lane = tid & 31, w = tid >> 5;

    if (tid < 32) {
        float s = gg1[tid] * rsqrtf(vg1[tid] + EPSBN);
        sS1[tid] = s; t1[tid] = bg1[tid] - mg1[tid] * s;
        s = gg2[tid] * rsqrtf(vg2[tid] + EPSBN);
        sS2[tid] = s; t2[tid] = bg2[tid] - mg2[tid] * s;
    }
    __syncthreads();
    for (int e = tid; e < 1024; e += 256) {
        int o = e >> 5, c = e & 31;
        sW1[o * 33 + c] = Wg1[e] * sS1[o];
        sW2[o * 33 + c] = Wg2[e] * sS2[o];
    }
    __syncthreads();

    int pt = blockIdx.x * 8 + w;                    // 0 .. B*N-1
    int b = pt >> 12;
    int idxv = (lane < KNN) ? g_idx[pt * KNN + lane] : 0;
    if (lane < 4)
        *(float4*)&sCtr[w][lane * 4] = *(const float4*)&g_hb[(size_t)pt * C_BOT + lane * 4];
#pragma unroll
    for (int t = 0; t < 3; t++) {                   // 80 float4 gathers
        int e = lane + t * 32;
        int row = (e < 80) ? (e >> 2) : 0;
        int ni = __shfl_sync(0xffffffffu, idxv, row);
        if (e < 80) {
            int q = e & 3;
            float4 v = *(const float4*)&g_hb[((size_t)(b << 12) + ni) * C_BOT + q * 4];
            *(float4*)&sNb[w][row * 16 + q * 4] = v;
        }
    }
    __syncwarp();

    float ctr[16];
#pragma unroll
    for (int c = 0; c < 16; c++) ctr[c] = sCtr[w][c];

    float cd1 = t1[lane], cd2 = t2[lane];
#pragma unroll
    for (int c = 0; c < 16; c++) {
        cd1 += sW1[lane * 33 + 16 + c] * ctr[c];
        cd2 += sW2[lane * 33 + 16 + c] * ctr[c];
    }
    float m1 = -FLT_MAX, m2 = -FLT_MAX;
#pragma unroll
    for (int k = 0; k < KNN; k++) {
        float a = cd1;
#pragma unroll
        for (int c = 0; c < 16; c++) a += sW1[lane * 33 + c] * sNb[w][k * 16 + c];
        a = a > 0.f ? a : 0.2f * a;
        m1 = fmaxf(m1, a);
        if ((k & 1) == 0) {
            float a2 = cd2;
#pragma unroll
            for (int c = 0; c < 16; c++) a2 += sW2[lane * 33 + c] * sNb[w][k * 16 + c];
            a2 = a2 > 0.f ? a2 : 0.2f * a2;
            m2 = fmaxf(m2, a2);
        }
    }
    float gm;
    if (lane < 16) {
        gm = -FLT_MAX;
#pragma unroll
        for (int k = 0; k < KNN; k++) gm = fmaxf(gm, sNb[w][k * 16 + lane]);
    } else {
        gm = ctr[lane - 16];
    }
    float* ap = g_allf + (size_t)pt * 96;
    ap[lane] = m1; ap[32 + lane] = m2; ap[64 + lane] = gm;
}

// -------- K4c: decoder+residual GEMM, 128o x 64n tiles ----------------------
#define FPAD 68
__global__ void __launch_bounds__(256) k_dec(const float* __restrict__ x,
                                             float* __restrict__ out)
{
    extern __shared__ float sm[];
    float* sW = sm;                     // 160*128
    float* sF = sW + 160 * 128;         // 16*FPAD
    float* sB = sF + 16 * FPAD;         // 256

    int tid = threadIdx.x;
    int b = blockIdx.y, n0 = blockIdx.x * 64;
    size_t gr0 = (size_t)b * N_PTS + n0;

    for (int e = tid; e < 160 * 128 / 4; e += 256)
        ((float4*)sW)[e] = ((const float4*)g_Wt)[e];
    sB[tid] = g_bias[tid];      // 256 threads cover 256
    __syncthreads();

    int to = tid & 31, tn = tid >> 5;   // o tile of 4, n tile of 8
    float acc[4][8];
    float res[4][8];

    // ---- phase 1: decoder, K=96 from allf ----
#pragma unroll
    for (int i = 0; i < 4; i++)
#pragma unroll
        for (int j = 0; j < 8; j++) acc[i][j] = 0.f;

    for (int kc = 0; kc < 6; kc++) {
        {
            int row = tid >> 2, q = tid & 3;
            float4 v = *(const float4*)&g_allf[(gr0 + row) * 96 + kc * 16 + q * 4];
            sF[(q * 4 + 0) * FPAD + row] = v.x;
            sF[(q * 4 + 1) * FPAD + row] = v.y;
            sF[(q * 4 + 2) * FPAD + row] = v.z;
            sF[(q * 4 + 3) * FPAD + row] = v.w;
        }
        __syncthreads();
#pragma unroll
        for (int k = 0; k < 16; k++) {
            float4 wv = *(float4*)&sW[(kc * 16 + k) * 128 + to * 4];
            float4 f0 = *(float4*)&sF[k * FPAD + tn * 8];
            float4 f1 = *(float4*)&sF[k * FPAD + tn * 8 + 4];
            float wr[4] = {wv.x, wv.y, wv.z, wv.w};
            float fr[8] = {f0.x, f0.y, f0.z, f0.w, f1.x, f1.y, f1.z, f1.w};
#pragma unroll
            for (int i = 0; i < 4; i++)
#pragma unroll
                for (int j = 0; j < 8; j++) acc[i][j] += wr[i] * fr[j];
        }
        __syncthreads();
    }
#pragma unroll
    for (int i = 0; i < 4; i++) {
        float bv = sB[to * 4 + i];
#pragma unroll
        for (int j = 0; j < 8; j++) {
            res[i][j] = fmaxf(acc[i][j] + bv, 0.f);
            acc[i][j] = 0.f;
        }
    }

    // ---- phase 2: residual, K=64 from x (coalesced channel rows) ----
    for (int kc = 0; kc < 4; kc++) {
        {
            int c = tid >> 4, nq = tid & 15;
            float4 v = *(const float4*)&x[((size_t)(b * C_IN + kc * 16 + c)) * N_PTS +
                                          n0 + nq * 4];
            *(float4*)&sF[c * FPAD + nq * 4] = v;
        }
        __syncthreads();
#pragma unroll
        for (int k = 0; k < 16; k++) {
            float4 wv = *(float4*)&sW[(96 + kc * 16 + k) * 128 + to * 4];
            float4 f0 = *(float4*)&sF[k * FPAD + tn * 8];
            float4 f1 = *(float4*)&sF[k * FPAD + tn * 8 + 4];
            float wr[4] = {wv.x, wv.y, wv.z, wv.w};
            float fr[8] = {f0.x, f0.y, f0.z, f0.w, f1.x, f1.y, f1.z, f1.w};
#pragma unroll
            for (int i = 0; i < 4; i++)
#pragma unroll
                for (int j = 0; j < 8; j++) acc[i][j] += wr[i] * fr[j];
        }
        __syncthreads();
    }

#pragma unroll
    for (int i = 0; i < 4; i++) {
        int o = to * 4 + i;
        float bv = sB[128 + o];
        float4 r0, r1;
        r0.x = res[i][0] + fmaxf(acc[i][0] + bv, 0.f);
        r0.y = res[i][1] + fmaxf(acc[i][1] + bv, 0.f);
        r0.z = res[i][2] + fmaxf(acc[i][2] + bv, 0.f);
        r0.w = res[i][3] + fmaxf(acc[i][3] + bv, 0.f);
        r1.x = res[i][4] + fmaxf(acc[i][4] + bv, 0.f);
        r1.y = res[i][5] + fmaxf(acc[i][5] + bv, 0.f);
        r1.z = res[i][6] + fmaxf(acc[i][6] + bv, 0.f);
        r1.w = res[i][7] + fmaxf(acc[i][7] + bv, 0.f);
        float* op = out + ((size_t)(b * C_OUT + o)) * N_PTS + n0 + tn * 8;
        *(float4*)op = r0;
        *(float4*)(op + 4) = r1;
    }
}

// ---------------- launch -----------------------------------------------------
extern "C" void kernel_launch(void* const* d_in, const int* in_sizes, int n_in,
                              void* d_out, int out_size)
{
    const float* x    = (const float*)d_in[0];
    const float* Wres = (const float*)d_in[1];
    const float* gres = (const float*)d_in[2];
    const float* bres = (const float*)d_in[3];
    const float* mres = (const float*)d_in[4];
    const float* vres = (const float*)d_in[5];
    const float* Wbot = (const float*)d_in[6];
    const float* gbot = (const float*)d_in[7];
    const float* bbot = (const float*)d_in[8];
    const float* mbot = (const float*)d_in[9];
    const float* vbot = (const float*)d_in[10];
    const float* Wg1  = (const float*)d_in[11];
    const float* gg1  = (const float*)d_in[12];
    const float* bg1  = (const float*)d_in[13];
    const float* mg1  = (const float*)d_in[14];
    const float* vg1  = (const float*)d_in[15];
    const float* Wg2  = (const float*)d_in[16];
    const float* gg2  = (const float*)d_in[17];
    const float* bg2  = (const float*)d_in[18];
    const float* mg2  = (const float*)d_in[19];
    const float* vg2  = (const float*)d_in[20];
    const float* Wdec = (const float*)d_in[21];
    const float* gdec = (const float*)d_in[22];
    const float* bdec = (const float*)d_in[23];
    const float* mdec = (const float*)d_in[24];
    const float* vdec = (const float*)d_in[25];
    float* out = (float*)d_out;

    size_t smem_dist = (64 * 128 * 2 + 256) * sizeof(float);
    cudaFuncSetAttribute(k_dist, cudaFuncAttributeMaxDynamicSharedMemorySize,
                         (int)smem_dist);
    size_t smem_dec = (160 * 128 + 16 * FPAD + 256) * sizeof(float);
    cudaFuncSetAttribute(k_dec, cudaFuncAttributeMaxDynamicSharedMemorySize,
                         (int)smem_dec);

    k_prep<<<(BATCH * N_PTS + 255) / 256, 256>>>(x, Wbot, gbot, bbot, mbot, vbot);
    k_fold<<<80, 256>>>(Wdec, gdec, bdec, mdec, vdec, Wres, gres, bres, mres, vres);
    k_dist<<<dim3(N_PTS / 128, N_PTS / 128, BATCH), 256, smem_dist>>>(x);
    k_topk<<<BATCH * N_PTS / 8, 256>>>();
    k_gcn<<<BATCH * N_PTS / 8, 256>>>(Wg1, gg1, bg1, mg1, vg1,
                                      Wg2, gg2, bg2, mg2, vg2);
    k_dec<<<dim3(N_PTS / 64, BATCH), 256, smem_dec>>>(x, out);
}

// round 11
// speedup vs baseline: 1.1099x; 1.1099x over previous
#include <cuda_runtime.h>
#include <math.h>
#include <float.h>

#define N_PTS 4096
#define BATCH 4
#define C_IN  64
#define C_OUT 128
#define KNN   20
#define C_BOT 16
#define EPSBN 1e-5f

// ---------------- scratch (device globals; no allocation) ----------------
__device__ float g_sq[BATCH * N_PTS];                       // 64 KB
__device__ float g_hb[BATCH * N_PTS * C_BOT];               // 1 MB, [B*N,16]
__device__ float g_d2[(size_t)BATCH * N_PTS * N_PTS];       // 256 MiB
__device__ float g_min16[(size_t)BATCH * N_PTS * 256];      // 16 MiB group minima
__device__ int   g_idx[BATCH * N_PTS * KNN];                // 1.3 MB
__device__ float g_allf[(size_t)BATCH * N_PTS * 96];        // 25 MB, [B*N,96]
__device__ float g_Wt[160 * 128];                           // folded [k][o]
__device__ float g_bias[256];                               // tDec[128], tRes[128]

// ---------------- f32x2 helpers (Blackwell packed FMA path) -----------------
__device__ __forceinline__ unsigned long long pk2(float x, float y) {
    unsigned long long r;
    asm("mov.b64 %0, {%1,%2};" : "=l"(r) : "f"(x), "f"(y));
    return r;
}
__device__ __forceinline__ void upk2(unsigned long long v, float& x, float& y) {
    asm("mov.b64 {%0,%1}, %2;" : "=f"(x), "=f"(y) : "l"(v));
}
__device__ __forceinline__ unsigned long long fma2(unsigned long long a,
                                                   unsigned long long b,
                                                   unsigned long long c) {
    unsigned long long d;
    asm("fma.rn.f32x2 %0, %1, %2, %3;" : "=l"(d) : "l"(a), "l"(b), "l"(c));
    return d;
}
__device__ __forceinline__ unsigned okey(float f) {
    unsigned u = __float_as_uint(f);
    return u ^ (unsigned)(((int)u >> 31) | 0x80000000);
}
__device__ __forceinline__ float unokey(unsigned k) {
    return __uint_as_float((k & 0x80000000u) ? (k ^ 0x80000000u) : ~k);
}

// warp bitonic sort ascending on packed u64 (32 lanes)
__device__ __forceinline__ unsigned long long bitonic32(unsigned long long p,
                                                        int lane) {
#pragma unroll
    for (int k2 = 2; k2 <= 32; k2 <<= 1) {
#pragma unroll
        for (int j = k2 >> 1; j > 0; j >>= 1) {
            unsigned long long q = __shfl_xor_sync(0xffffffffu, p, j);
            bool up = ((lane & k2) == 0);
            bool lower = ((lane & j) == 0);
            bool takeMin = (up == lower);
            bool qs = q < p;
            p = (takeMin == qs) ? q : p;
        }
    }
    return p;
}

// insert cand into sorted 32-lane list p (ascending); returns new p
__device__ __forceinline__ unsigned long long wins(unsigned long long p,
                                                   unsigned long long cand,
                                                   int lane) {
    unsigned pm = __ballot_sync(0xffffffffu, p < cand);
    int pos = __popc(pm);
    unsigned long long up = __shfl_up_sync(0xffffffffu, p, 1);
    if (lane == pos)      p = cand;
    else if (lane > pos)  p = up;
    return p;
}

// ---------------- K1: sq norms + bottleneck conv (BN+ReLU), hb transposed ----
__global__ void k_prep(const float* __restrict__ x,
                       const float* __restrict__ Wb, const float* __restrict__ gb,
                       const float* __restrict__ bb, const float* __restrict__ mb,
                       const float* __restrict__ vb)
{
    __shared__ float sW[C_BOT][C_IN];
    __shared__ float sS[C_BOT], sT[C_BOT];
    int tid = threadIdx.x;
    if (tid < C_BOT) {
        float s = gb[tid] * rsqrtf(vb[tid] + EPSBN);
        sS[tid] = s;
        sT[tid] = bb[tid] - mb[tid] * s;
    }
    for (int e = tid; e < C_BOT * C_IN; e += blockDim.x)
        sW[e >> 6][e & 63] = Wb[e];
    __syncthreads();

    int g = blockIdx.x * blockDim.x + tid;      // 0 .. BATCH*N_PTS-1
    if (g >= BATCH * N_PTS) return;
    int b = g >> 12, n = g & (N_PTS - 1);
    const float* xp = x + (size_t)b * C_IN * N_PTS + n;

    float xc[C_IN];
    float sq = 0.f;
#pragma unroll
    for (int c = 0; c < C_IN; c++) {
        float v = xp[(size_t)c * N_PTS];
        xc[c] = v;
        sq += v * v;                 // same ascending-c order as GEMM dot
    }
    g_sq[g] = sq;

#pragma unroll
    for (int o = 0; o < C_BOT; o++) {
        float acc = 0.f;
#pragma unroll
        for (int c = 0; c < C_IN; c++) acc += sW[o][c] * xc[c];
        float h = acc * sS[o] + sT[o];
        g_hb[(size_t)g * C_BOT + o] = fmaxf(h, 0.f);
    }
}

// ------- K2: pairwise distances, 128x128 tile, 8x8/thread f32x2 + group mins
__global__ void __launch_bounds__(256) k_dist(const float* __restrict__ x)
{
    extern __shared__ float smd[];
    float* As  = smd;                  // 64*128
    float* Bs  = As + 64 * 128;        // 64*128
    float* sqA = Bs + 64 * 128;        // 128
    float* sqB = sqA + 128;            // 128

    int b  = blockIdx.z;
    int bi = blockIdx.y;
    int bj = blockIdx.x;
    int tid = threadIdx.x;
    const float* xb = x + (size_t)b * C_IN * N_PTS;

    for (int e = tid; e < 64 * 32; e += 256) {
        int k = e >> 5, i = e & 31;
        ((float4*)As)[k * 32 + i] =
            *(const float4*)&xb[(size_t)k * N_PTS + bi * 128 + i * 4];
        ((float4*)Bs)[k * 32 + i] =
            *(const float4*)&xb[(size_t)k * N_PTS + bj * 128 + i * 4];
    }
    if (tid < 128)      sqA[tid]       = g_sq[b * N_PTS + bi * 128 + tid];
    else                sqB[tid - 128] = g_sq[b * N_PTS + bj * 128 + (tid - 128)];
    __syncthreads();

    int tx = tid & 15, ty = tid >> 4;
    const float4* As4 = (const float4*)As;
    const unsigned long long* Bs8 = (const unsigned long long*)Bs;

    unsigned long long acc2[8][4];
#pragma unroll
    for (int i = 0; i < 8; i++)
#pragma unroll
        for (int j = 0; j < 4; j++) acc2[i][j] = 0ULL;

#pragma unroll 2
    for (int k = 0; k < 64; k++) {
        float4 a0 = As4[k * 32 + ty * 2];
        float4 a1 = As4[k * 32 + ty * 2 + 1];
        unsigned long long B0 = Bs8[k * 64 + tx * 4 + 0];
        unsigned long long B1 = Bs8[k * 64 + tx * 4 + 1];
        unsigned long long B2 = Bs8[k * 64 + tx * 4 + 2];
        unsigned long long B3 = Bs8[k * 64 + tx * 4 + 3];
        unsigned long long A[8];
        A[0] = pk2(a0.x, a0.x); A[1] = pk2(a0.y, a0.y);
        A[2] = pk2(a0.z, a0.z); A[3] = pk2(a0.w, a0.w);
        A[4] = pk2(a1.x, a1.x); A[5] = pk2(a1.y, a1.y);
        A[6] = pk2(a1.z, a1.z); A[7] = pk2(a1.w, a1.w);
#pragma unroll
        for (int i = 0; i < 8; i++) {
            acc2[i][0] = fma2(A[i], B0, acc2[i][0]);
            acc2[i][1] = fma2(A[i], B1, acc2[i][1]);
            acc2[i][2] = fma2(A[i], B2, acc2[i][2]);
            acc2[i][3] = fma2(A[i], B3, acc2[i][3]);
        }
    }

#pragma unroll
    for (int ri = 0; ri < 8; ri++) {
        int r = ty * 8 + ri;
        float sr = sqA[r];
        float c0, c1;
        float4 v0, v1;
        upk2(acc2[ri][0], c0, c1);
        v0.x = sr + sqB[tx * 8 + 0] - 2.f * c0;
        v0.y = sr + sqB[tx * 8 + 1] - 2.f * c1;
        upk2(acc2[ri][1], c0, c1);
        v0.z = sr + sqB[tx * 8 + 2] - 2.f * c0;
        v0.w = sr + sqB[tx * 8 + 3] - 2.f * c1;
        upk2(acc2[ri][2], c0, c1);
        v1.x = sr + sqB[tx * 8 + 4] - 2.f * c0;
        v1.y = sr + sqB[tx * 8 + 5] - 2.f * c1;
        upk2(acc2[ri][3], c0, c1);
        v1.z = sr + sqB[tx * 8 + 6] - 2.f * c0;
        v1.w = sr + sqB[tx * 8 + 7] - 2.f * c1;
        float* dp = g_d2 + ((size_t)(b * N_PTS + bi * 128 + r)) * N_PTS +
                    bj * 128 + tx * 8;
        *(float4*)dp = v0;
        *(float4*)(dp + 4) = v1;

        // per-row 16-element group minimum (2 adjacent tx threads per group)
        float mn = fminf(fminf(fminf(v0.x, v0.y), fminf(v0.z, v0.w)),
                         fminf(fminf(v1.x, v1.y), fminf(v1.z, v1.w)));
        float mo = __shfl_xor_sync(0xffffffffu, mn, 1);
        mn = fminf(mn, mo);
        if ((tx & 1) == 0)
            g_min16[((size_t)(b * N_PTS + bi * 128 + r)) * 256 + bj * 8 +
                    (tx >> 1)] = mn;
    }
}

// -------- K3: planned top-K — pick best groups first, batch their loads -----
__global__ void __launch_bounds__(256) k_topk()
{
    int lane = threadIdx.x & 31, w = threadIdx.x >> 5;
    int row = blockIdx.x * 8 + w;              // b*N + n
    const float* dp = g_d2 + (size_t)row * N_PTS;
    const float* gm = g_min16 + (size_t)row * 256;

    // ---- load all 256 group mins into registers ----
    float mreg[8];
#pragma unroll
    for (int c = 0; c < 8; c++) mreg[c] = gm[c * 32 + lane];

    // ---- Phase A: 20 smallest group-mins (ordering heuristic, exact set) ----
    unsigned long long pa =
        ((unsigned long long)okey(mreg[0]) << 32) | (unsigned)lane;
    pa = bitonic32(pa, lane);
    unsigned long long thrA = __shfl_sync(0xffffffffu, pa, KNN - 1);
    float thrAf = unokey((unsigned)(thrA >> 32));
#pragma unroll 1
    for (int c = 1; c < 8; c++) {
        float m = mreg[c];
        unsigned hit = __ballot_sync(0xffffffffu, m <= thrAf);
        while (hit) {
            int s = __ffs(hit) - 1;
            hit &= hit - 1;
            float ms = __shfl_sync(0xffffffffu, m, s);
            unsigned long long pn = ((unsigned long long)okey(ms) << 32) |
                                    (unsigned)(c * 32 + s);
            if (pn < thrA) {
                pa = wins(pa, pn, lane);
                thrA = __shfl_sync(0xffffffffu, pa, KNN - 1);
                thrAf = unokey((unsigned)(thrA >> 32));
            }
        }
    }
    unsigned gidA = (unsigned)(pa & 0xFFFFFFFFULL);   // sorted group ids

    // ---- Phase B init: fetch groups gidA[0..1], bitonic sort 32 elements ----
    unsigned g0 = __shfl_sync(0xffffffffu, gidA, 0);
    unsigned g1 = __shfl_sync(0xffffffffu, gidA, 1);
    unsigned gsel0 = (lane < 16) ? g0 : g1;
    unsigned eidx0 = gsel0 * 16 + (lane & 15);
    float ev0 = dp[eidx0];

    // ---- Phase B: batched independent loads for groups gidA[2..19] ----
    float bv[9];
    unsigned gsel[9];
#pragma unroll
    for (int r = 0; r < 9; r++) {
        gsel[r] = __shfl_sync(0xffffffffu, gidA, 2 + 2 * r + (lane >> 4));
        bv[r] = dp[gsel[r] * 16 + (lane & 15)];
    }

    unsigned long long p =
        ((unsigned long long)okey(ev0) << 32) | eidx0;
    p = bitonic32(p, lane);
    unsigned long long thr = __shfl_sync(0xffffffffu, p, KNN - 1);
    float thrF = unokey((unsigned)(thr >> 32));

#pragma unroll 1
    for (int r = 0; r < 9; r++) {
        float v = bv[r];
        unsigned uk = okey(v);
        unsigned hit = __ballot_sync(0xffffffffu, v <= thrF);
        while (hit) {
            int s = __ffs(hit) - 1;
            hit &= hit - 1;
            unsigned ks = __shfl_sync(0xffffffffu, uk, s);
            unsigned gs = __shfl_sync(0xffffffffu, gsel[r], s);
            unsigned long long pn = ((unsigned long long)ks << 32) |
                                    (gs * 16 + (s & 15));
            if (pn < thr) {
                p = wins(p, pn, lane);
                thr = __shfl_sync(0xffffffffu, p, KNN - 1);
                thrF = unokey((unsigned)(thr >> 32));
            }
        }
    }

    // ---- Phase C: rescan all group mins vs final threshold ----
#pragma unroll 1
    for (int c = 0; c < 8; c++) {
        float m = mreg[c];
        unsigned hit = __ballot_sync(0xffffffffu, m <= thrF);
        while (hit) {
            int s = __ffs(hit) - 1;
            hit &= hit - 1;
            float ms = __shfl_sync(0xffffffffu, m, s);
            if (ms > thrF) continue;           // tightened since ballot
            unsigned g = (unsigned)(c * 32 + s);
            if (__ballot_sync(0xffffffffu, lane < KNN && gidA == g))
                continue;                      // already processed in Phase B
            float v2 = dp[g * 16 + (lane & 15)];
            unsigned uk2 = okey(v2);
            unsigned h2 = __ballot_sync(0xffffffffu, (lane < 16) && (v2 <= thrF));
            while (h2) {
                int s2 = __ffs(h2) - 1;
                h2 &= h2 - 1;
                unsigned ks = __shfl_sync(0xffffffffu, uk2, s2);
                unsigned long long pn = ((unsigned long long)ks << 32) |
                                        (g * 16 + s2);
                if (pn < thr) {
                    p = wins(p, pn, lane);
                    thr = __shfl_sync(0xffffffffu, p, KNN - 1);
                    thrF = unokey((unsigned)(thr >> 32));
                }
            }
        }
    }

    if (lane < KNN)
        g_idx[row * KNN + lane] = (int)(p & 0xFFFFFFFFULL);
}

// -------- K4a: fold decoder+residual weights (BN scale) into g_Wt -----------
__global__ void k_fold(const float* __restrict__ Wdec, const float* __restrict__ gdec,
                       const float* __restrict__ bdec, const float* __restrict__ mdec,
                       const float* __restrict__ vdec,
                       const float* __restrict__ Wres, const float* __restrict__ gres,
                       const float* __restrict__ bres, const float* __restrict__ mres,
                       const float* __restrict__ vres)
{
    int tid = blockIdx.x * blockDim.x + threadIdx.x;
    for (int e = tid; e < 160 * 128; e += gridDim.x * blockDim.x) {
        int k = e >> 7, o = e & 127;
        float wv;
        if (k < 96) wv = Wdec[o * 96 + k] * (gdec[o] * rsqrtf(vdec[o] + EPSBN));
        else        wv = Wres[o * 64 + (k - 96)] * (gres[o] * rsqrtf(vres[o] + EPSBN));
        g_Wt[e] = wv;
    }
    if (tid < 128) {
        float sd = gdec[tid] * rsqrtf(vdec[tid] + EPSBN);
        g_bias[tid] = bdec[tid] - mdec[tid] * sd;
        float sr = gres[tid] * rsqrtf(vres[tid] + EPSBN);
        g_bias[128 + tid] = bres[tid] - mres[tid] * sr;
    }
}

// -------- K4b: GCN branches + gmax, one warp per point ----------------------
__global__ void __launch_bounds__(256) k_gcn(
    const float* __restrict__ Wg1, const float* __restrict__ gg1,
    const float* __restrict__ bg1, const float* __restrict__ mg1,
    const float* __restrict__ vg1,
    const float* __restrict__ Wg2, const float* __restrict__ gg2,
    const float* __restrict__ bg2, const float* __restrict__ mg2,
    const float* __restrict__ vg2)
{
    __shared__ float sW1[32 * 33], sW2[32 * 33];
    __shared__ float sS1[32], sS2[32], t1[32], t2[32];
    __shared__ float sNb[8][KNN * 16];
    __shared__ float sCtr[8][16];

    int tid = threadIdx.x, lane = tid & 31, w = tid >> 5;

    if (tid < 32) {
        float s = gg1[tid] * rsqrtf(vg1[tid] + EPSBN);
        sS1[tid] = s; t1[tid] = bg1[tid] - mg1[tid] * s;
        s = gg2[tid] * rsqrtf(vg2[tid] + EPSBN);
        sS2[tid] = s; t2[tid] = bg2[tid] - mg2[tid] * s;
    }
    __syncthreads();
    for (int e = tid; e < 1024; e += 256) {
        int o = e >> 5, c = e & 31;
        sW1[o * 33 + c] = Wg1[e] * sS1[o];
        sW2[o * 33 + c] = Wg2[e] * sS2[o];
    }
    __syncthreads();

    int pt = blockIdx.x * 8 + w;                    // 0 .. B*N-1
    int b = pt >> 12;
    int idxv = (lane < KNN) ? g_idx[pt * KNN + lane] : 0;
    if (lane < 4)
        *(float4*)&sCtr[w][lane * 4] = *(const float4*)&g_hb[(size_t)pt * C_BOT + lane * 4];
#pragma unroll
    for (int t = 0; t < 3; t++) {                   // 80 float4 gathers
        int e = lane + t * 32;
        int row = (e < 80) ? (e >> 2) : 0;
        int ni = __shfl_sync(0xffffffffu, idxv, row);
        if (e < 80) {
            int q = e & 3;
            float4 v = *(const float4*)&g_hb[((size_t)(b << 12) + ni) * C_BOT + q * 4];
            *(float4*)&sNb[w][row * 16 + q * 4] = v;
        }
    }
    __syncwarp();

    float ctr[16];
#pragma unroll
    for (int c = 0; c < 16; c++) ctr[c] = sCtr[w][c];

    float cd1 = t1[lane], cd2 = t2[lane];
#pragma unroll
    for (int c = 0; c < 16; c++) {
        cd1 += sW1[lane * 33 + 16 + c] * ctr[c];
        cd2 += sW2[lane * 33 + 16 + c] * ctr[c];
    }
    float m1 = -FLT_MAX, m2 = -FLT_MAX;
#pragma unroll
    for (int k = 0; k < KNN; k++) {
        float a = cd1;
#pragma unroll
        for (int c = 0; c < 16; c++) a += sW1[lane * 33 + c] * sNb[w][k * 16 + c];
        a = a > 0.f ? a : 0.2f * a;
        m1 = fmaxf(m1, a);
        if ((k & 1) == 0) {
            float a2 = cd2;
#pragma unroll
            for (int c = 0; c < 16; c++) a2 += sW2[lane * 33 + c] * sNb[w][k * 16 + c];
            a2 = a2 > 0.f ? a2 : 0.2f * a2;
            m2 = fmaxf(m2, a2);
        }
    }
    float gm;
    if (lane < 16) {
        gm = -FLT_MAX;
#pragma unroll
        for (int k = 0; k < KNN; k++) gm = fmaxf(gm, sNb[w][k * 16 + lane]);
    } else {
        gm = ctr[lane - 16];
    }
    float* ap = g_allf + (size_t)pt * 96;
    ap[lane] = m1; ap[32 + lane] = m2; ap[64 + lane] = gm;
}

// -------- K4c: decoder+residual GEMM, 128o x 64n tiles ----------------------
#define FPAD 68
__global__ void __launch_bounds__(256) k_dec(const float* __restrict__ x,
                                             float* __restrict__ out)
{
    extern __shared__ float sm[];
    float* sW = sm;                     // 160*128
    float* sF = sW + 160 * 128;         // 16*FPAD
    float* sB = sF + 16 * FPAD;         // 256

    int tid = threadIdx.x;
    int b = blockIdx.y, n0 = blockIdx.x * 64;
    size_t gr0 = (size_t)b * N_PTS + n0;

    for (int e = tid; e < 160 * 128 / 4; e += 256)
        ((float4*)sW)[e] = ((const float4*)g_Wt)[e];
    sB[tid] = g_bias[tid];      // 256 threads cover 256
    __syncthreads();

    int to = tid & 31, tn = tid >> 5;   // o tile of 4, n tile of 8
    float acc[4][8];
    float res[4][8];

    // ---- phase 1: decoder, K=96 from allf ----
#pragma unroll
    for (int i = 0; i < 4; i++)
#pragma unroll
        for (int j = 0; j < 8; j++) acc[i][j] = 0.f;

    for (int kc = 0; kc < 6; kc++) {
        {
            int row = tid >> 2, q = tid & 3;
            float4 v = *(const float4*)&g_allf[(gr0 + row) * 96 + kc * 16 + q * 4];
            sF[(q * 4 + 0) * FPAD + row] = v.x;
            sF[(q * 4 + 1) * FPAD + row] = v.y;
            sF[(q * 4 + 2) * FPAD + row] = v.z;
            sF[(q * 4 + 3) * FPAD + row] = v.w;
        }
        __syncthreads();
#pragma unroll
        for (int k = 0; k < 16; k++) {
            float4 wv = *(float4*)&sW[(kc * 16 + k) * 128 + to * 4];
            float4 f0 = *(float4*)&sF[k * FPAD + tn * 8];
            float4 f1 = *(float4*)&sF[k * FPAD + tn * 8 + 4];
            float wr[4] = {wv.x, wv.y, wv.z, wv.w};
            float fr[8] = {f0.x, f0.y, f0.z, f0.w, f1.x, f1.y, f1.z, f1.w};
#pragma unroll
            for (int i = 0; i < 4; i++)
#pragma unroll
                for (int j = 0; j < 8; j++) acc[i][j] += wr[i] * fr[j];
        }
        __syncthreads();
    }
#pragma unroll
    for (int i = 0; i < 4; i++) {
        float bv = sB[to * 4 + i];
#pragma unroll
        for (int j = 0; j < 8; j++) {
            res[i][j] = fmaxf(acc[i][j] + bv, 0.f);
            acc[i][j] = 0.f;
        }
    }

    // ---- phase 2: residual, K=64 from x (coalesced channel rows) ----
    for (int kc = 0; kc < 4; kc++) {
        {
            int c = tid >> 4, nq = tid & 15;
            float4 v = *(const float4*)&x[((size_t)(b * C_IN + kc * 16 + c)) * N_PTS +
                                          n0 + nq * 4];
            *(float4*)&sF[c * FPAD + nq * 4] = v;
        }
        __syncthreads();
#pragma unroll
        for (int k = 0; k < 16; k++) {
            float4 wv = *(float4*)&sW[(96 + kc * 16 + k) * 128 + to * 4];
            float4 f0 = *(float4*)&sF[k * FPAD + tn * 8];
            float4 f1 = *(float4*)&sF[k * FPAD + tn * 8 + 4];
            float wr[4] = {wv.x, wv.y, wv.z, wv.w};
            float fr[8] = {f0.x, f0.y, f0.z, f0.w, f1.x, f1.y, f1.z, f1.w};
#pragma unroll
            for (int i = 0; i < 4; i++)
#pragma unroll
                for (int j = 0; j < 8; j++) acc[i][j] += wr[i] * fr[j];
        }
        __syncthreads();
    }

#pragma unroll
    for (int i = 0; i < 4; i++) {
        int o = to * 4 + i;
        float bv = sB[128 + o];
        float4 r0, r1;
        r0.x = res[i][0] + fmaxf(acc[i][0] + bv, 0.f);
        r0.y = res[i][1] + fmaxf(acc[i][1] + bv, 0.f);
        r0.z = res[i][2] + fmaxf(acc[i][2] + bv, 0.f);
        r0.w = res[i][3] + fmaxf(acc[i][3] + bv, 0.f);
        r1.x = res[i][4] + fmaxf(acc[i][4] + bv, 0.f);
        r1.y = res[i][5] + fmaxf(acc[i][5] + bv, 0.f);
        r1.z = res[i][6] + fmaxf(acc[i][6] + bv, 0.f);
        r1.w = res[i][7] + fmaxf(acc[i][7] + bv, 0.f);
        float* op = out + ((size_t)(b * C_OUT + o)) * N_PTS + n0 + tn * 8;
        *(float4*)op = r0;
        *(float4*)(op + 4) = r1;
    }
}

// ---------------- launch -----------------------------------------------------
extern "C" void kernel_launch(void* const* d_in, const int* in_sizes, int n_in,
                              void* d_out, int out_size)
{
    const float* x    = (const float*)d_in[0];
    const float* Wres = (const float*)d_in[1];
    const float* gres = (const float*)d_in[2];
    const float* bres = (const float*)d_in[3];
    const float* mres = (const float*)d_in[4];
    const float* vres = (const float*)d_in[5];
    const float* Wbot = (const float*)d_in[6];
    const float* gbot = (const float*)d_in[7];
    const float* bbot = (const float*)d_in[8];
    const float* mbot = (const float*)d_in[9];
    const float* vbot = (const float*)d_in[10];
    const float* Wg1  = (const float*)d_in[11];
    const float* gg1  = (const float*)d_in[12];
    const float* bg1  = (const float*)d_in[13];
    const float* mg1  = (const float*)d_in[14];
    const float* vg1  = (const float*)d_in[15];
    const float* Wg2  = (const float*)d_in[16];
    const float* gg2  = (const float*)d_in[17];
    const float* bg2  = (const float*)d_in[18];
    const float* mg2  = (const float*)d_in[19];
    const float* vg2  = (const float*)d_in[20];
    const float* Wdec = (const float*)d_in[21];
    const float* gdec = (const float*)d_in[22];
    const float* bdec = (const float*)d_in[23];
    const float* mdec = (const float*)d_in[24];
    const float* vdec = (const float*)d_in[25];
    float* out = (float*)d_out;

    size_t smem_dist = (64 * 128 * 2 + 256) * sizeof(float);
    cudaFuncSetAttribute(k_dist, cudaFuncAttributeMaxDynamicSharedMemorySize,
                         (int)smem_dist);
    size_t smem_dec = (160 * 128 + 16 * FPAD + 256) * sizeof(float);
    cudaFuncSetAttribute(k_dec, cudaFuncAttributeMaxDynamicSharedMemorySize,
                         (int)smem_dec);

    k_prep<<<(BATCH * N_PTS + 255) / 256, 256>>>(x, Wbot, gbot, bbot, mbot, vbot);
    k_fold<<<80, 256>>>(Wdec, gdec, bdec, mdec, vdec, Wres, gres, bres, mres, vres);
    k_dist<<<dim3(N_PTS / 128, N_PTS / 128, BATCH), 256, smem_dist>>>(x);
    k_topk<<<BATCH * N_PTS / 8, 256>>>();
    k_gcn<<<BATCH * N_PTS / 8, 256>>>(Wg1, gg1, bg1, mg1, vg1,
                                      Wg2, gg2, bg2, mg2, vg2);
    k_dec<<<dim3(N_PTS / 64, BATCH), 256, smem_dec>>>(x, out);
}

// round 13
// speedup vs baseline: 1.3181x; 1.1876x over previous
#include <cuda_runtime.h>
#include <math.h>
#include <float.h>

#define N_PTS 4096
#define BATCH 4
#define C_IN  64
#define C_OUT 128
#define KNN   20
#define C_BOT 16
#define EPSBN 1e-5f

// ---------------- scratch (device globals; no allocation) ----------------
__device__ float g_sq[BATCH * N_PTS];
__device__ float g_hb[BATCH * N_PTS * C_BOT];
__device__ float g_d2[(size_t)BATCH * N_PTS * N_PTS];
__device__ float g_min16[(size_t)BATCH * N_PTS * 256];
__device__ int   g_idx[BATCH * N_PTS * KNN];
__device__ float g_allf[(size_t)BATCH * N_PTS * 96];
__device__ float g_Wt[160 * 128];
__device__ float g_bias[256];

// ---------------- f32x2 helpers (Blackwell packed FMA path) -----------------
__device__ __forceinline__ unsigned long long pk2(float x, float y) {
    unsigned long long r;
    asm("mov.b64 %0, {%1,%2};" : "=l"(r) : "f"(x), "f"(y));
    return r;
}
__device__ __forceinline__ void upk2(unsigned long long v, float& x, float& y) {
    asm("mov.b64 {%0,%1}, %2;" : "=f"(x), "=f"(y) : "l"(v));
}
__device__ __forceinline__ unsigned long long fma2(unsigned long long a,
                                                   unsigned long long b,
                                                   unsigned long long c) {
    unsigned long long d;
    asm("fma.rn.f32x2 %0, %1, %2, %3;" : "=l"(d) : "l"(a), "l"(b), "l"(c));
    return d;
}
__device__ __forceinline__ unsigned okey(float f) {
    unsigned u = __float_as_uint(f);
    return u ^ (unsigned)(((int)u >> 31) | 0x80000000);
}
__device__ __forceinline__ float unokey(unsigned k) {
    return __uint_as_float((k & 0x80000000u) ? (k ^ 0x80000000u) : ~k);
}
__device__ __forceinline__ unsigned long long bitonic32(unsigned long long p,
                                                        int lane) {
#pragma unroll
    for (int k2 = 2; k2 <= 32; k2 <<= 1) {
#pragma unroll
        for (int j = k2 >> 1; j > 0; j >>= 1) {
            unsigned long long q = __shfl_xor_sync(0xffffffffu, p, j);
            bool up = ((lane & k2) == 0);
            bool lower = ((lane & j) == 0);
            bool takeMin = (up == lower);
            bool qs = q < p;
            p = (takeMin == qs) ? q : p;
        }
    }
    return p;
}
__device__ __forceinline__ unsigned long long wins(unsigned long long p,
                                                   unsigned long long cand,
                                                   int lane) {
    unsigned pm = __ballot_sync(0xffffffffu, p < cand);
    int pos = __popc(pm);
    unsigned long long up = __shfl_up_sync(0xffffffffu, p, 1);
    if (lane == pos)      p = cand;
    else if (lane > pos)  p = up;
    return p;
}

// ---------------- K1: sq norms + bottleneck conv (BN+ReLU) ------------------
__global__ void k_prep(const float* __restrict__ x,
                       const float* __restrict__ Wb, const float* __restrict__ gb,
                       const float* __restrict__ bb, const float* __restrict__ mb,
                       const float* __restrict__ vb)
{
    __shared__ float sW[C_BOT][C_IN];
    __shared__ float sS[C_BOT], sT[C_BOT];
    int tid = threadIdx.x;
    if (tid < C_BOT) {
        float s = gb[tid] * rsqrtf(vb[tid] + EPSBN);
        sS[tid] = s;
        sT[tid] = bb[tid] - mb[tid] * s;
    }
    for (int e = tid; e < C_BOT * C_IN; e += blockDim.x)
        sW[e >> 6][e & 63] = Wb[e];
    __syncthreads();

    int g = blockIdx.x * blockDim.x + tid;
    if (g >= BATCH * N_PTS) return;
    int b = g >> 12, n = g & (N_PTS - 1);
    const float* xp = x + (size_t)b * C_IN * N_PTS + n;

    float xc[C_IN];
    float sq = 0.f;
#pragma unroll
    for (int c = 0; c < C_IN; c++) {
        float v = xp[(size_t)c * N_PTS];
        xc[c] = v;
        sq += v * v;                 // same ascending-c order as GEMM dot
    }
    g_sq[g] = sq;

#pragma unroll
    for (int o = 0; o < C_BOT; o++) {
        float acc = 0.f;
#pragma unroll
        for (int c = 0; c < C_IN; c++) acc += sW[o][c] * xc[c];
        float h = acc * sS[o] + sT[o];
        g_hb[(size_t)g * C_BOT + o] = fmaxf(h, 0.f);
    }
}

// ------- K2: SYMMETRIC pairwise distances: upper-triangle tiles only --------
// smem layout (floats): [Ts 128*132 (overlays As@0, Bs@8192)] [Cm 128*9] [sqA 128] [sqB 128]
#define TSPAD 132
#define SM_CM  (128 * TSPAD)
#define SM_SQA (SM_CM + 128 * 9)
#define SM_SQB (SM_SQA + 128)
#define SM_DIST_FLOATS (SM_SQB + 128)

__global__ void __launch_bounds__(256) k_dist(const float* __restrict__ x)
{
    extern __shared__ float smd[];
    float* As  = smd;                  // 64*128 (phase 1)
    float* Bs  = smd + 8192;           // 64*128 (phase 1)
    float* Ts  = smd;                  // 128*TSPAD (phase 2, overlays As/Bs)
    float* Cm  = smd + SM_CM;          // 128*9 column group-mins
    float* sqA = smd + SM_SQA;
    float* sqB = smd + SM_SQB;

    int b  = blockIdx.z;
    int bi = blockIdx.y;
    int bj = blockIdx.x;
    if (bj < bi) return;               // lower triangle handled by mirror
    int tid = threadIdx.x;
    const float* xb = x + (size_t)b * C_IN * N_PTS;

    for (int e = tid; e < 64 * 32; e += 256) {
        int k = e >> 5, i = e & 31;
        ((float4*)As)[k * 32 + i] =
            *(const float4*)&xb[(size_t)k * N_PTS + bi * 128 + i * 4];
        ((float4*)Bs)[k * 32 + i] =
            *(const float4*)&xb[(size_t)k * N_PTS + bj * 128 + i * 4];
    }
    if (tid < 128)      sqA[tid]       = g_sq[b * N_PTS + bi * 128 + tid];
    else                sqB[tid - 128] = g_sq[b * N_PTS + bj * 128 + (tid - 128)];
    __syncthreads();

    int tx = tid & 15, ty = tid >> 4;
    const float4* As4 = (const float4*)As;
    const unsigned long long* Bs8 = (const unsigned long long*)Bs;

    unsigned long long acc2[8][4];
#pragma unroll
    for (int i = 0; i < 8; i++)
#pragma unroll
        for (int j = 0; j < 4; j++) acc2[i][j] = 0ULL;

#pragma unroll 2
    for (int k = 0; k < 64; k++) {
        float4 a0 = As4[k * 32 + ty * 2];
        float4 a1 = As4[k * 32 + ty * 2 + 1];
        unsigned long long B0 = Bs8[k * 64 + tx * 4 + 0];
        unsigned long long B1 = Bs8[k * 64 + tx * 4 + 1];
        unsigned long long B2 = Bs8[k * 64 + tx * 4 + 2];
        unsigned long long B3 = Bs8[k * 64 + tx * 4 + 3];
        unsigned long long A[8];
        A[0] = pk2(a0.x, a0.x); A[1] = pk2(a0.y, a0.y);
        A[2] = pk2(a0.z, a0.z); A[3] = pk2(a0.w, a0.w);
        A[4] = pk2(a1.x, a1.x); A[5] = pk2(a1.y, a1.y);
        A[6] = pk2(a1.z, a1.z); A[7] = pk2(a1.w, a1.w);
#pragma unroll
        for (int i = 0; i < 8; i++) {
            acc2[i][0] = fma2(A[i], B0, acc2[i][0]);
            acc2[i][1] = fma2(A[i], B1, acc2[i][1]);
            acc2[i][2] = fma2(A[i], B2, acc2[i][2]);
            acc2[i][3] = fma2(A[i], B3, acc2[i][3]);
        }
    }
    __syncthreads();                   // all warps done reading As/Bs

    float cm[8];
#pragma unroll
    for (int q = 0; q < 8; q++) cm[q] = __int_as_float(0x7f800000);

#pragma unroll
    for (int ri = 0; ri < 8; ri++) {
        int r = ty * 8 + ri;
        float sr = sqA[r];
        float c0, c1;
        float4 v0, v1;
        upk2(acc2[ri][0], c0, c1);
        v0.x = sr + sqB[tx * 8 + 0] - 2.f * c0;
        v0.y = sr + sqB[tx * 8 + 1] - 2.f * c1;
        upk2(acc2[ri][1], c0, c1);
        v0.z = sr + sqB[tx * 8 + 2] - 2.f * c0;
        v0.w = sr + sqB[tx * 8 + 3] - 2.f * c1;
        upk2(acc2[ri][2], c0, c1);
        v1.x = sr + sqB[tx * 8 + 4] - 2.f * c0;
        v1.y = sr + sqB[tx * 8 + 5] - 2.f * c1;
        upk2(acc2[ri][3], c0, c1);
        v1.z = sr + sqB[tx * 8 + 6] - 2.f * c0;
        v1.w = sr + sqB[tx * 8 + 7] - 2.f * c1;

        float* dp = g_d2 + ((size_t)(b * N_PTS + bi * 128 + r)) * N_PTS +
                    bj * 128 + tx * 8;
        *(float4*)dp = v0;
        *(float4*)(dp + 4) = v1;

        // stage for mirror
        *(float4*)&Ts[r * TSPAD + tx * 8] = v0;
        *(float4*)&Ts[r * TSPAD + tx * 8 + 4] = v1;

        // original per-row group mins
        float mn = fminf(fminf(fminf(v0.x, v0.y), fminf(v0.z, v0.w)),
                         fminf(fminf(v1.x, v1.y), fminf(v1.z, v1.w)));
        float mo = __shfl_xor_sync(0xffffffffu, mn, 1);
        mn = fminf(mn, mo);
        if ((tx & 1) == 0)
            g_min16[((size_t)(b * N_PTS + bi * 128 + r)) * 256 + bj * 8 +
                    (tx >> 1)] = mn;

        // column partial mins (for mirror group mins)
        cm[0] = fminf(cm[0], v0.x); cm[1] = fminf(cm[1], v0.y);
        cm[2] = fminf(cm[2], v0.z); cm[3] = fminf(cm[3], v0.w);
        cm[4] = fminf(cm[4], v1.x); cm[5] = fminf(cm[5], v1.y);
        cm[6] = fminf(cm[6], v1.z); cm[7] = fminf(cm[7], v1.w);
    }

    if (bi == bj) return;              // diagonal: no mirror needed

    // combine ty-pair column mins (rows ty*8..ty*8+7 with partner) -> 16-chunk
#pragma unroll
    for (int q = 0; q < 8; q++) {
        float o = __shfl_xor_sync(0xffffffffu, cm[q], 16);
        cm[q] = fminf(cm[q], o);
    }
    if ((ty & 1) == 0) {
#pragma unroll
        for (int q = 0; q < 8; q++)
            Cm[(tx * 8 + q) * 9 + (ty >> 1)] = cm[q];
    }
    __syncthreads();                   // Ts + Cm complete

    // mirror d2 tile: row m = original column, cols = original rows
#pragma unroll
    for (int ri = 0; ri < 8; ri++) {
        int m = ty * 8 + ri;
        float* op = g_d2 + ((size_t)(b * N_PTS + bj * 128 + m)) * N_PTS +
                    bi * 128;
#pragma unroll
        for (int q = 0; q < 8; q++)
            op[tx + 16 * q] = Ts[(tx + 16 * q) * TSPAD + m];
    }
    // mirror group mins (coalesced)
    for (int e = tid; e < 1024; e += 256) {
        int m = e >> 3, j = e & 7;
        g_min16[((size_t)(b * N_PTS + bj * 128 + m)) * 256 + bi * 8 + j] =
            Cm[m * 9 + j];
    }
}

// -------- K3: planned top-K — pick best groups first, batch their loads -----
__global__ void __launch_bounds__(256) k_topk()
{
    int lane = threadIdx.x & 31, w = threadIdx.x >> 5;
    int row = blockIdx.x * 8 + w;
    const float* dp = g_d2 + (size_t)row * N_PTS;
    const float* gm = g_min16 + (size_t)row * 256;

    float mreg[8];
#pragma unroll
    for (int c = 0; c < 8; c++) mreg[c] = gm[c * 32 + lane];

    // Phase A: 20 smallest group-mins
    unsigned long long pa =
        ((unsigned long long)okey(mreg[0]) << 32) | (unsigned)lane;
    pa = bitonic32(pa, lane);
    unsigned long long thrA = __shfl_sync(0xffffffffu, pa, KNN - 1);
    float thrAf = unokey((unsigned)(thrA >> 32));
#pragma unroll 1
    for (int c = 1; c < 8; c++) {
        float m = mreg[c];
        unsigned hit = __ballot_sync(0xffffffffu, m <= thrAf);
        while (hit) {
            int s = __ffs(hit) - 1;
            hit &= hit - 1;
            float ms = __shfl_sync(0xffffffffu, m, s);
            unsigned long long pn = ((unsigned long long)okey(ms) << 32) |
                                    (unsigned)(c * 32 + s);
            if (pn < thrA) {
                pa = wins(pa, pn, lane);
                thrA = __shfl_sync(0xffffffffu, pa, KNN - 1);
                thrAf = unokey((unsigned)(thrA >> 32));
            }
        }
    }
    unsigned gidA = (unsigned)(pa & 0xFFFFFFFFULL);

    // Phase B init: two best groups -> bitonic 32-sort
    unsigned g0 = __shfl_sync(0xffffffffu, gidA, 0);
    unsigned g1 = __shfl_sync(0xffffffffu, gidA, 1);
    unsigned gsel0 = (lane < 16) ? g0 : g1;
    unsigned eidx0 = gsel0 * 16 + (lane & 15);
    float ev0 = dp[eidx0];

    float bv[9];
    unsigned gsel[9];
#pragma unroll
    for (int r = 0; r < 9; r++) {
        gsel[r] = __shfl_sync(0xffffffffu, gidA, 2 + 2 * r + (lane >> 4));
        bv[r] = dp[gsel[r] * 16 + (lane & 15)];
    }

    unsigned long long p = ((unsigned long long)okey(ev0) << 32) | eidx0;
    p = bitonic32(p, lane);
    unsigned long long thr = __shfl_sync(0xffffffffu, p, KNN - 1);
    float thrF = unokey((unsigned)(thr >> 32));

#pragma unroll 1
    for (int r = 0; r < 9; r++) {
        float v = bv[r];
        unsigned uk = okey(v);
        unsigned hit = __ballot_sync(0xffffffffu, v <= thrF);
        while (hit) {
            int s = __ffs(hit) - 1;
            hit &= hit - 1;
            unsigned ks = __shfl_sync(0xffffffffu, uk, s);
            unsigned gs = __shfl_sync(0xffffffffu, gsel[r], s);
            unsigned long long pn = ((unsigned long long)ks << 32) |
                                    (gs * 16 + (s & 15));
            if (pn < thr) {
                p = wins(p, pn, lane);
                thr = __shfl_sync(0xffffffffu, p, KNN - 1);
                thrF = unokey((unsigned)(thr >> 32));
            }
        }
    }

    // Phase C: rescan all group mins vs final threshold
#pragma unroll 1
    for (int c = 0; c < 8; c++) {
        float m = mreg[c];
        unsigned hit = __ballot_sync(0xffffffffu, m <= thrF);
        while (hit) {
            int s = __ffs(hit) - 1;
            hit &= hit - 1;
            float ms = __shfl_sync(0xffffffffu, m, s);
            if (ms > thrF) continue;
            unsigned g = (unsigned)(c * 32 + s);
            if (__ballot_sync(0xffffffffu, lane < KNN && gidA == g))
                continue;
            float v2 = dp[g * 16 + (lane & 15)];
            unsigned uk2 = okey(v2);
            unsigned h2 = __ballot_sync(0xffffffffu, (lane < 16) && (v2 <= thrF));
            while (h2) {
                int s2 = __ffs(h2) - 1;
                h2 &= h2 - 1;
                unsigned ks = __shfl_sync(0xffffffffu, uk2, s2);
                unsigned long long pn = ((unsigned long long)ks << 32) |
                                        (g * 16 + s2);
                if (pn < thr) {
                    p = wins(p, pn, lane);
                    thr = __shfl_sync(0xffffffffu, p, KNN - 1);
                    thrF = unokey((unsigned)(thr >> 32));
                }
            }
        }
    }

    if (lane < KNN)
        g_idx[row * KNN + lane] = (int)(p & 0xFFFFFFFFULL);
}

// -------- K4a: fold decoder+residual weights (BN scale) into g_Wt -----------
__global__ void k_fold(const float* __restrict__ Wdec, const float* __restrict__ gdec,
                       const float* __restrict__ bdec, const float* __restrict__ mdec,
                       const float* __restrict__ vdec,
                       const float* __restrict__ Wres, const float* __restrict__ gres,
                       const float* __restrict__ bres, const float* __restrict__ mres,
                       const float* __restrict__ vres)
{
    int tid = blockIdx.x * blockDim.x + threadIdx.x;
    for (int e = tid; e < 160 * 128; e += gridDim.x * blockDim.x) {
        int k = e >> 7, o = e & 127;
        float wv;
        if (k < 96) wv = Wdec[o * 96 + k] * (gdec[o] * rsqrtf(vdec[o] + EPSBN));
        else        wv = Wres[o * 64 + (k - 96)] * (gres[o] * rsqrtf(vres[o] + EPSBN));
        g_Wt[e] = wv;
    }
    if (tid < 128) {
        float sd = gdec[tid] * rsqrtf(vdec[tid] + EPSBN);
        g_bias[tid] = bdec[tid] - mdec[tid] * sd;
        float sr = gres[tid] * rsqrtf(vres[tid] + EPSBN);
        g_bias[128 + tid] = bres[tid] - mres[tid] * sr;
    }
}

// -------- K4b: GCN branches + gmax, one warp per point ----------------------
__global__ void __launch_bounds__(256) k_gcn(
    const float* __restrict__ Wg1, const float* __restrict__ gg1,
    const float* __restrict__ bg1, const float* __restrict__ mg1,
    const float* __restrict__ vg1,
    const float* __restrict__ Wg2, const float* __restrict__ gg2,
    const float* __restrict__ bg2, const float* __restrict__ mg2,
    const float* __restrict__ vg2)
{
    __shared__ float sW1[32 * 33], sW2[32 * 33];
    __shared__ float sS1[32], sS2[32], t1[32], t2[32];
    __shared__ float sNb[8][KNN * 16];
    __shared__ float sCtr[8][16];

    int tid = threadIdx.x, lane = tid & 31, w = tid >> 5;

    if (tid < 32) {
        float s = gg1[tid] * rsqrtf(vg1[tid] + EPSBN);
        sS1[tid] = s; t1[tid] = bg1[tid] - mg1[tid] * s;
        s = gg2[tid] * rsqrtf(vg2[tid] + EPSBN);
        sS2[tid] = s; t2[tid] = bg2[tid] - mg2[tid] * s;
    }
    __syncthreads();
    for (int e = tid; e < 1024; e += 256) {
        int o = e >> 5, c = e & 31;
        sW1[o * 33 + c] = Wg1[e] * sS1[o];
        sW2[o * 33 + c] = Wg2[e] * sS2[o];
    }
    __syncthreads();

    int pt = blockIdx.x * 8 + w;
    int b = pt >> 12;
    int idxv = (lane < KNN) ? g_idx[pt * KNN + lane] : 0;
    if (lane < 4)
        *(float4*)&sCtr[w][lane * 4] = *(const float4*)&g_hb[(size_t)pt * C_BOT + lane * 4];
#pragma unroll
    for (int t = 0; t < 3; t++) {
        int e = lane + t * 32;
        int row = (e < 80) ? (e >> 2) : 0;
        int ni = __shfl_sync(0xffffffffu, idxv, row);
        if (e < 80) {
            int q = e & 3;
            float4 v = *(const float4*)&g_hb[((size_t)(b << 12) + ni) * C_BOT + q * 4];
            *(float4*)&sNb[w][row * 16 + q * 4] = v;
        }
    }
    __syncwarp();

    float ctr[16];
#pragma unroll
    for (int c = 0; c < 16; c++) ctr[c] = sCtr[w][c];

    float cd1 = t1[lane], cd2 = t2[lane];
#pragma unroll
    for (int c = 0; c < 16; c++) {
        cd1 += sW1[lane * 33 + 16 + c] * ctr[c];
        cd2 += sW2[lane * 33 + 16 + c] * ctr[c];
    }
    float m1 = -FLT_MAX, m2 = -FLT_MAX;
#pragma unroll
    for (int k = 0; k < KNN; k++) {
        float a = cd1;
#pragma unroll
        for (int c = 0; c < 16; c++) a += sW1[lane * 33 + c] * sNb[w][k * 16 + c];
        a = a > 0.f ? a : 0.2f * a;
        m1 = fmaxf(m1, a);
        if ((k & 1) == 0) {
            float a2 = cd2;
#pragma unroll
            for (int c = 0; c < 16; c++) a2 += sW2[lane * 33 + c] * sNb[w][k * 16 + c];
            a2 = a2 > 0.f ? a2 : 0.2f * a2;
            m2 = fmaxf(m2, a2);
        }
    }
    float gmx;
    if (lane < 16) {
        gmx = -FLT_MAX;
#pragma unroll
        for (int k = 0; k < KNN; k++) gmx = fmaxf(gmx, sNb[w][k * 16 + lane]);
    } else {
        gmx = ctr[lane - 16];
    }
    float* ap = g_allf + (size_t)pt * 96;
    ap[lane] = m1; ap[32 + lane] = m2; ap[64 + lane] = gmx;
}

// -------- K4c: decoder+residual GEMM, 128o x 64n tiles ----------------------
#define FPAD 68
__global__ void __launch_bounds__(256) k_dec(const float* __restrict__ x,
                                             float* __restrict__ out)
{
    extern __shared__ float sm[];
    float* sW = sm;
    float* sF = sW + 160 * 128;
    float* sB = sF + 16 * FPAD;

    int tid = threadIdx.x;
    int b = blockIdx.y, n0 = blockIdx.x * 64;
    size_t gr0 = (size_t)b * N_PTS + n0;

    for (int e = tid; e < 160 * 128 / 4; e += 256)
        ((float4*)sW)[e] = ((const float4*)g_Wt)[e];
    sB[tid] = g_bias[tid];
    __syncthreads();

    int to = tid & 31, tn = tid >> 5;
    float acc[4][8];
    float res[4][8];

#pragma unroll
    for (int i = 0; i < 4; i++)
#pragma unroll
        for (int j = 0; j < 8; j++) acc[i][j] = 0.f;

    for (int kc = 0; kc < 6; kc++) {
        {
            int row = tid >> 2, q = tid & 3;
            float4 v = *(const float4*)&g_allf[(gr0 + row) * 96 + kc * 16 + q * 4];
            sF[(q * 4 + 0) * FPAD + row] = v.x;
            sF[(q * 4 + 1) * FPAD + row] = v.y;
            sF[(q * 4 + 2) * FPAD + row] = v.z;
            sF[(q * 4 + 3) * FPAD + row] = v.w;
        }
        __syncthreads();
#pragma unroll
        for (int k = 0; k < 16; k++) {
            float4 wv = *(float4*)&sW[(kc * 16 + k) * 128 + to * 4];
            float4 f0 = *(float4*)&sF[k * FPAD + tn * 8];
            float4 f1 = *(float4*)&sF[k * FPAD + tn * 8 + 4];
            float wr[4] = {wv.x, wv.y, wv.z, wv.w};
            float fr[8] = {f0.x, f0.y, f0.z, f0.w, f1.x, f1.y, f1.z, f1.w};
#pragma unroll
            for (int i = 0; i < 4; i++)
#pragma unroll
                for (int j = 0; j < 8; j++) acc[i][j] += wr[i] * fr[j];
        }
        __syncthreads();
    }
#pragma unroll
    for (int i = 0; i < 4; i++) {
        float bv = sB[to * 4 + i];
#pragma unroll
        for (int j = 0; j < 8; j++) {
            res[i][j] = fmaxf(acc[i][j] + bv, 0.f);
            acc[i][j] = 0.f;
        }
    }

    for (int kc = 0; kc < 4; kc++) {
        {
            int c = tid >> 4, nq = tid & 15;
            float4 v = *(const float4*)&x[((size_t)(b * C_IN + kc * 16 + c)) * N_PTS +
                                          n0 + nq * 4];
            *(float4*)&sF[c * FPAD + nq * 4] = v;
        }
        __syncthreads();
#pragma unroll
        for (int k = 0; k < 16; k++) {
            float4 wv = *(float4*)&sW[(96 + kc * 16 + k) * 128 + to * 4];
            float4 f0 = *(float4*)&sF[k * FPAD + tn * 8];
            float4 f1 = *(float4*)&sF[k * FPAD + tn * 8 + 4];
            float wr[4] = {wv.x, wv.y, wv.z, wv.w};
            float fr[8] = {f0.x, f0.y, f0.z, f0.w, f1.x, f1.y, f1.z, f1.w};
#pragma unroll
            for (int i = 0; i < 4; i++)
#pragma unroll
                for (int j = 0; j < 8; j++) acc[i][j] += wr[i] * fr[j];
        }
        __syncthreads();
    }

#pragma unroll
    for (int i = 0; i < 4; i++) {
        int o = to * 4 + i;
        float bv = sB[128 + o];
        float4 r0, r1;
        r0.x = res[i][0] + fmaxf(acc[i][0] + bv, 0.f);
        r0.y = res[i][1] + fmaxf(acc[i][1] + bv, 0.f);
        r0.z = res[i][2] + fmaxf(acc[i][2] + bv, 0.f);
        r0.w = res[i][3] + fmaxf(acc[i][3] + bv, 0.f);
        r1.x = res[i][4] + fmaxf(acc[i][4] + bv, 0.f);
        r1.y = res[i][5] + fmaxf(acc[i][5] + bv, 0.f);
        r1.z = res[i][6] + fmaxf(acc[i][6] + bv, 0.f);
        r1.w = res[i][7] + fmaxf(acc[i][7] + bv, 0.f);
        float* op = out + ((size_t)(b * C_OUT + o)) * N_PTS + n0 + tn * 8;
        *(float4*)op = r0;
        *(float4*)(op + 4) = r1;
    }
}

// ---------------- launch -----------------------------------------------------
extern "C" void kernel_launch(void* const* d_in, const int* in_sizes, int n_in,
                              void* d_out, int out_size)
{
    const float* x    = (const float*)d_in[0];
    const float* Wres = (const float*)d_in[1];
    const float* gres = (const float*)d_in[2];
    const float* bres = (const float*)d_in[3];
    const float* mres = (const float*)d_in[4];
    const float* vres = (const float*)d_in[5];
    const float* Wbot = (const float*)d_in[6];
    const float* gbot = (const float*)d_in[7];
    const float* bbot = (const float*)d_in[8];
    const float* mbot = (const float*)d_in[9];
    const float* vbot = (const float*)d_in[10];
    const float* Wg1  = (const float*)d_in[11];
    const float* gg1  = (const float*)d_in[12];
    const float* bg1  = (const float*)d_in[13];
    const float* mg1  = (const float*)d_in[14];
    const float* vg1  = (const float*)d_in[15];
    const float* Wg2  = (const float*)d_in[16];
    const float* gg2  = (const float*)d_in[17];
    const float* bg2  = (const float*)d_in[18];
    const float* mg2  = (const float*)d_in[19];
    const float* vg2  = (const float*)d_in[20];
    const float* Wdec = (const float*)d_in[21];
    const float* gdec = (const float*)d_in[22];
    const float* bdec = (const float*)d_in[23];
    const float* mdec = (const float*)d_in[24];
    const float* vdec = (const float*)d_in[25];
    float* out = (float*)d_out;

    size_t smem_dist = SM_DIST_FLOATS * sizeof(float);
    cudaFuncSetAttribute(k_dist, cudaFuncAttributeMaxDynamicSharedMemorySize,
                         (int)smem_dist);
    size_t smem_dec = (160 * 128 + 16 * FPAD + 256) * sizeof(float);
    cudaFuncSetAttribute(k_dec, cudaFuncAttributeMaxDynamicSharedMemorySize,
                         (int)smem_dec);

    k_prep<<<(BATCH * N_PTS + 255) / 256, 256>>>(x, Wbot, gbot, bbot, mbot, vbot);
    k_fold<<<80, 256>>>(Wdec, gdec, bdec, mdec, vdec, Wres, gres, bres, mres, vres);
    k_dist<<<dim3(N_PTS / 128, N_PTS / 128, BATCH), 256, smem_dist>>>(x);
    k_topk<<<BATCH * N_PTS / 8, 256>>>();
    k_gcn<<<BATCH * N_PTS / 8, 256>>>(Wg1, gg1, bg1, mg1, vg1,
                                      Wg2, gg2, bg2, mg2, vg2);
    k_dec<<<dim3(N_PTS / 64, BATCH), 256, smem_dec>>>(x, out);
}

// round 15
// speedup vs baseline: 1.3708x; 1.0400x over previous
#include <cuda_runtime.h>
#include <math.h>
#include <float.h>

#define N_PTS 4096
#define BATCH 4
#define C_IN  64
#define C_OUT 128
#define KNN   20
#define C_BOT 16
#define EPSBN 1e-5f

// ---------------- scratch (device globals; no allocation) ----------------
__device__ float g_sq[BATCH * N_PTS];
__device__ float g_hb[BATCH * N_PTS * C_BOT];
__device__ float g_d2[(size_t)BATCH * N_PTS * N_PTS];
__device__ float g_min16[(size_t)BATCH * N_PTS * 256];
__device__ int   g_idx[BATCH * N_PTS * KNN];
__device__ float g_allf[(size_t)BATCH * N_PTS * 96];
__device__ float g_Wt[160 * 128];
__device__ float g_bias[256];

// ---------------- f32x2 helpers (Blackwell packed FMA path) -----------------
__device__ __forceinline__ unsigned long long pk2(float x, float y) {
    unsigned long long r;
    asm("mov.b64 %0, {%1,%2};" : "=l"(r) : "f"(x), "f"(y));
    return r;
}
__device__ __forceinline__ void upk2(unsigned long long v, float& x, float& y) {
    asm("mov.b64 {%0,%1}, %2;" : "=f"(x), "=f"(y) : "l"(v));
}
__device__ __forceinline__ unsigned long long fma2(unsigned long long a,
                                                   unsigned long long b,
                                                   unsigned long long c) {
    unsigned long long d;
    asm("fma.rn.f32x2 %0, %1, %2, %3;" : "=l"(d) : "l"(a), "l"(b), "l"(c));
    return d;
}
__device__ __forceinline__ unsigned okey(float f) {
    unsigned u = __float_as_uint(f);
    return u ^ (unsigned)(((int)u >> 31) | 0x80000000);
}
__device__ __forceinline__ float unokey(unsigned k) {
    return __uint_as_float((k & 0x80000000u) ? (k ^ 0x80000000u) : ~k);
}
__device__ __forceinline__ unsigned long long bitonic32(unsigned long long p,
                                                        int lane) {
#pragma unroll
    for (int k2 = 2; k2 <= 32; k2 <<= 1) {
#pragma unroll
        for (int j = k2 >> 1; j > 0; j >>= 1) {
            unsigned long long q = __shfl_xor_sync(0xffffffffu, p, j);
            bool up = ((lane & k2) == 0);
            bool lower = ((lane & j) == 0);
            bool takeMin = (up == lower);
            bool qs = q < p;
            p = (takeMin == qs) ? q : p;
        }
    }
    return p;
}
__device__ __forceinline__ unsigned long long wins(unsigned long long p,
                                                   unsigned long long cand,
                                                   int lane) {
    unsigned pm = __ballot_sync(0xffffffffu, p < cand);
    int pos = __popc(pm);
    unsigned long long up = __shfl_up_sync(0xffffffffu, p, 1);
    if (lane == pos)      p = cand;
    else if (lane > pos)  p = up;
    return p;
}

// ------ K1: sq norms + bottleneck conv (BN+ReLU) + weight fold (block 64) ---
__global__ void k_prep(const float* __restrict__ x,
                       const float* __restrict__ Wb, const float* __restrict__ gb,
                       const float* __restrict__ bb, const float* __restrict__ mb,
                       const float* __restrict__ vb,
                       const float* __restrict__ Wdec, const float* __restrict__ gdec,
                       const float* __restrict__ bdec, const float* __restrict__ mdec,
                       const float* __restrict__ vdec,
                       const float* __restrict__ Wres, const float* __restrict__ gres,
                       const float* __restrict__ bres, const float* __restrict__ mres,
                       const float* __restrict__ vres)
{
    int tid = threadIdx.x;
    if (blockIdx.x == 64) {            // weight-fold block
        for (int e = tid; e < 160 * 128; e += 256) {
            int k = e >> 7, o = e & 127;
            float wv;
            if (k < 96) wv = Wdec[o * 96 + k] * (gdec[o] * rsqrtf(vdec[o] + EPSBN));
            else        wv = Wres[o * 64 + (k - 96)] * (gres[o] * rsqrtf(vres[o] + EPSBN));
            g_Wt[e] = wv;
        }
        if (tid < 128) {
            float sd = gdec[tid] * rsqrtf(vdec[tid] + EPSBN);
            g_bias[tid] = bdec[tid] - mdec[tid] * sd;
            float sr = gres[tid] * rsqrtf(vres[tid] + EPSBN);
            g_bias[128 + tid] = bres[tid] - mres[tid] * sr;
        }
        return;
    }

    __shared__ float sW[C_BOT][C_IN];
    __shared__ float sS[C_BOT], sT[C_BOT];
    if (tid < C_BOT) {
        float s = gb[tid] * rsqrtf(vb[tid] + EPSBN);
        sS[tid] = s;
        sT[tid] = bb[tid] - mb[tid] * s;
    }
    for (int e = tid; e < C_BOT * C_IN; e += blockDim.x)
        sW[e >> 6][e & 63] = Wb[e];
    __syncthreads();

    int g = blockIdx.x * blockDim.x + tid;
    int b = g >> 12, n = g & (N_PTS - 1);
    const float* xp = x + (size_t)b * C_IN * N_PTS + n;

    float xc[C_IN];
    float sq = 0.f;
#pragma unroll
    for (int c = 0; c < C_IN; c++) {
        float v = xp[(size_t)c * N_PTS];
        xc[c] = v;
        sq += v * v;                 // same ascending-c order as GEMM dot
    }
    g_sq[g] = sq;

#pragma unroll
    for (int o = 0; o < C_BOT; o++) {
        float acc = 0.f;
#pragma unroll
        for (int c = 0; c < C_IN; c++) acc += sW[o][c] * xc[c];
        float h = acc * sS[o] + sT[o];
        g_hb[(size_t)g * C_BOT + o] = fmaxf(h, 0.f);
    }
}

// ------- K2: SYMMETRIC pairwise distances: upper-triangle tiles only --------
#define TSPAD 132
#define SM_CM  (128 * TSPAD)
#define SM_SQA (SM_CM + 128 * 9)
#define SM_SQB (SM_SQA + 128)
#define SM_DIST_FLOATS (SM_SQB + 128)

__global__ void __launch_bounds__(256) k_dist(const float* __restrict__ x)
{
    extern __shared__ float smd[];
    float* As  = smd;                  // 64*128 (phase 1)
    float* Bs  = smd + 8192;           // 64*128 (phase 1)
    float* Ts  = smd;                  // 128*TSPAD (phase 2, overlays As/Bs)
    float* Cm  = smd + SM_CM;          // 128*9 column group-mins
    float* sqA = smd + SM_SQA;
    float* sqB = smd + SM_SQB;

    int b  = blockIdx.z;
    int bi = blockIdx.y;
    int bj = blockIdx.x;
    if (bj < bi) return;
    int tid = threadIdx.x;
    const float* xb = x + (size_t)b * C_IN * N_PTS;

    for (int e = tid; e < 64 * 32; e += 256) {
        int k = e >> 5, i = e & 31;
        ((float4*)As)[k * 32 + i] =
            *(const float4*)&xb[(size_t)k * N_PTS + bi * 128 + i * 4];
        ((float4*)Bs)[k * 32 + i] =
            *(const float4*)&xb[(size_t)k * N_PTS + bj * 128 + i * 4];
    }
    if (tid < 128)      sqA[tid]       = g_sq[b * N_PTS + bi * 128 + tid];
    else                sqB[tid - 128] = g_sq[b * N_PTS + bj * 128 + (tid - 128)];
    __syncthreads();

    int tx = tid & 15, ty = tid >> 4;
    const float4* As4 = (const float4*)As;
    const unsigned long long* Bs8 = (const unsigned long long*)Bs;

    unsigned long long acc2[8][4];
#pragma unroll
    for (int i = 0; i < 8; i++)
#pragma unroll
        for (int j = 0; j < 4; j++) acc2[i][j] = 0ULL;

#pragma unroll 2
    for (int k = 0; k < 64; k++) {
        float4 a0 = As4[k * 32 + ty * 2];
        float4 a1 = As4[k * 32 + ty * 2 + 1];
        unsigned long long B0 = Bs8[k * 64 + tx * 4 + 0];
        unsigned long long B1 = Bs8[k * 64 + tx * 4 + 1];
        unsigned long long B2 = Bs8[k * 64 + tx * 4 + 2];
        unsigned long long B3 = Bs8[k * 64 + tx * 4 + 3];
        unsigned long long A[8];
        A[0] = pk2(a0.x, a0.x); A[1] = pk2(a0.y, a0.y);
        A[2] = pk2(a0.z, a0.z); A[3] = pk2(a0.w, a0.w);
        A[4] = pk2(a1.x, a1.x); A[5] = pk2(a1.y, a1.y);
        A[6] = pk2(a1.z, a1.z); A[7] = pk2(a1.w, a1.w);
#pragma unroll
        for (int i = 0; i < 8; i++) {
            acc2[i][0] = fma2(A[i], B0, acc2[i][0]);
            acc2[i][1] = fma2(A[i], B1, acc2[i][1]);
            acc2[i][2] = fma2(A[i], B2, acc2[i][2]);
            acc2[i][3] = fma2(A[i], B3, acc2[i][3]);
        }
    }
    __syncthreads();

    float cm[8];
#pragma unroll
    for (int q = 0; q < 8; q++) cm[q] = __int_as_float(0x7f800000);

#pragma unroll
    for (int ri = 0; ri < 8; ri++) {
        int r = ty * 8 + ri;
        float sr = sqA[r];
        float c0, c1;
        float4 v0, v1;
        upk2(acc2[ri][0], c0, c1);
        v0.x = sr + sqB[tx * 8 + 0] - 2.f * c0;
        v0.y = sr + sqB[tx * 8 + 1] - 2.f * c1;
        upk2(acc2[ri][1], c0, c1);
        v0.z = sr + sqB[tx * 8 + 2] - 2.f * c0;
        v0.w = sr + sqB[tx * 8 + 3] - 2.f * c1;
        upk2(acc2[ri][2], c0, c1);
        v1.x = sr + sqB[tx * 8 + 4] - 2.f * c0;
        v1.y = sr + sqB[tx * 8 + 5] - 2.f * c1;
        upk2(acc2[ri][3], c0, c1);
        v1.z = sr + sqB[tx * 8 + 6] - 2.f * c0;
        v1.w = sr + sqB[tx * 8 + 7] - 2.f * c1;

        float* dp = g_d2 + ((size_t)(b * N_PTS + bi * 128 + r)) * N_PTS +
                    bj * 128 + tx * 8;
        *(float4*)dp = v0;
        *(float4*)(dp + 4) = v1;

        *(float4*)&Ts[r * TSPAD + tx * 8] = v0;
        *(float4*)&Ts[r * TSPAD + tx * 8 + 4] = v1;

        float mn = fminf(fminf(fminf(v0.x, v0.y), fminf(v0.z, v0.w)),
                         fminf(fminf(v1.x, v1.y), fminf(v1.z, v1.w)));
        float mo = __shfl_xor_sync(0xffffffffu, mn, 1);
        mn = fminf(mn, mo);
        if ((tx & 1) == 0)
            g_min16[((size_t)(b * N_PTS + bi * 128 + r)) * 256 + bj * 8 +
                    (tx >> 1)] = mn;

        cm[0] = fminf(cm[0], v0.x); cm[1] = fminf(cm[1], v0.y);
        cm[2] = fminf(cm[2], v0.z); cm[3] = fminf(cm[3], v0.w);
        cm[4] = fminf(cm[4], v1.x); cm[5] = fminf(cm[5], v1.y);
        cm[6] = fminf(cm[6], v1.z); cm[7] = fminf(cm[7], v1.w);
    }

    if (bi == bj) return;

#pragma unroll
    for (int q = 0; q < 8; q++) {
        float o = __shfl_xor_sync(0xffffffffu, cm[q], 16);
        cm[q] = fminf(cm[q], o);
    }
    if ((ty & 1) == 0) {
#pragma unroll
        for (int q = 0; q < 8; q++)
            Cm[(tx * 8 + q) * 9 + (ty >> 1)] = cm[q];
    }
    __syncthreads();

#pragma unroll
    for (int ri = 0; ri < 8; ri++) {
        int m = ty * 8 + ri;
        float* op = g_d2 + ((size_t)(b * N_PTS + bj * 128 + m)) * N_PTS +
                    bi * 128;
#pragma unroll
        for (int q = 0; q < 8; q++)
            op[tx + 16 * q] = Ts[(tx + 16 * q) * TSPAD + m];
    }
    for (int e = tid; e < 1024; e += 256) {
        int m = e >> 3, j = e & 7;
        g_min16[((size_t)(b * N_PTS + bj * 128 + m)) * 256 + bi * 8 + j] =
            Cm[m * 9 + j];
    }
}

// -------- K3: planned top-K, heuristic lane-min planning (exact result) -----
__global__ void __launch_bounds__(256) k_topk()
{
    int lane = threadIdx.x & 31, w = threadIdx.x >> 5;
    int row = blockIdx.x * 8 + w;
    const float* dp = g_d2 + (size_t)row * N_PTS;
    const float* gm = g_min16 + (size_t)row * 256;

    float mreg[8];
#pragma unroll
    for (int c = 0; c < 8; c++) mreg[c] = gm[c * 32 + lane];

    // Phase A (heuristic, no insertions): sort the 32 lane-mins
    float mv = mreg[0];
    int cix = 0;
#pragma unroll
    for (int c = 1; c < 8; c++)
        if (mreg[c] < mv) { mv = mreg[c]; cix = c; }
    unsigned long long pa =
        ((unsigned long long)okey(mv) << 32) | (unsigned)(cix * 32 + lane);
    pa = bitonic32(pa, lane);
    unsigned gidA = (unsigned)(pa & 0xFFFFFFFFULL);   // planned groups (ranks 0-19)

    // Phase B init: two best planned groups -> bitonic 32-sort
    unsigned g0 = __shfl_sync(0xffffffffu, gidA, 0);
    unsigned g1 = __shfl_sync(0xffffffffu, gidA, 1);
    unsigned gsel0 = (lane < 16) ? g0 : g1;
    unsigned eidx0 = gsel0 * 16 + (lane & 15);
    float ev0 = dp[eidx0];

    float bv[9];
    unsigned gsel[9];
#pragma unroll
    for (int r = 0; r < 9; r++) {
        gsel[r] = __shfl_sync(0xffffffffu, gidA, 2 + 2 * r + (lane >> 4));
        bv[r] = dp[gsel[r] * 16 + (lane & 15)];
    }

    unsigned long long p = ((unsigned long long)okey(ev0) << 32) | eidx0;
    p = bitonic32(p, lane);
    unsigned long long thr = __shfl_sync(0xffffffffu, p, KNN - 1);
    float thrF = unokey((unsigned)(thr >> 32));

#pragma unroll 1
    for (int r = 0; r < 9; r++) {
        float v = bv[r];
        unsigned uk = okey(v);
        unsigned hit = __ballot_sync(0xffffffffu, v <= thrF);
        while (hit) {
            int s = __ffs(hit) - 1;
            hit &= hit - 1;
            unsigned ks = __shfl_sync(0xffffffffu, uk, s);
            unsigned gs = __shfl_sync(0xffffffffu, gsel[r], s);
            unsigned long long pn = ((unsigned long long)ks << 32) |
                                    (gs * 16 + (s & 15));
            if (pn < thr) {
                p = wins(p, pn, lane);
                thr = __shfl_sync(0xffffffffu, p, KNN - 1);
                thrF = unokey((unsigned)(thr >> 32));
            }
        }
    }

    // Phase C: rescan all group mins vs final threshold (exactness)
#pragma unroll 1
    for (int c = 0; c < 8; c++) {
        float m = mreg[c];
        unsigned hit = __ballot_sync(0xffffffffu, m <= thrF);
        while (hit) {
            int s = __ffs(hit) - 1;
            hit &= hit - 1;
            float ms = __shfl_sync(0xffffffffu, m, s);
            if (ms > thrF) continue;
            unsigned g = (unsigned)(c * 32 + s);
            if (__ballot_sync(0xffffffffu, lane < KNN && gidA == g))
                continue;                  // fetched in Phase B
            float v2 = dp[g * 16 + (lane & 15)];
            unsigned uk2 = okey(v2);
            unsigned h2 = __ballot_sync(0xffffffffu, (lane < 16) && (v2 <= thrF));
            while (h2) {
                int s2 = __ffs(h2) - 1;
                h2 &= h2 - 1;
                unsigned ks = __shfl_sync(0xffffffffu, uk2, s2);
                unsigned long long pn = ((unsigned long long)ks << 32) |
                                        (g * 16 + s2);
                if (pn < thr) {
                    p = wins(p, pn, lane);
                    thr = __shfl_sync(0xffffffffu, p, KNN - 1);
                    thrF = unokey((unsigned)(thr >> 32));
                }
            }
        }
    }

    if (lane < KNN)
        g_idx[row * KNN + lane] = (int)(p & 0xFFFFFFFFULL);
}

// -------- K4b: GCN branches + gmax, one warp per point ----------------------
__global__ void __launch_bounds__(256) k_gcn(
    const float* __restrict__ Wg1, const float* __restrict__ gg1,
    const float* __restrict__ bg1, const float* __restrict__ mg1,
    const float* __restrict__ vg1,
    const float* __restrict__ Wg2, const float* __restrict__ gg2,
    const float* __restrict__ bg2, const float* __restrict__ mg2,
    const float* __restrict__ vg2)
{
    __shared__ float sW1[32 * 33], sW2[32 * 33];
    __shared__ float sS1[32], sS2[32], t1[32], t2[32];
    __shared__ float sNb[8][KNN * 16];
    __shared__ float sCtr[8][16];

    int tid = threadIdx.x, lane = tid & 31, w = tid >> 5;

    if (tid < 32) {
        float s = gg1[tid] * rsqrtf(vg1[tid] + EPSBN);
        sS1[tid] = s; t1[tid] = bg1[tid] - mg1[tid] * s;
        s = gg2[tid] * rsqrtf(vg2[tid] + EPSBN);
        sS2[tid] = s; t2[tid] = bg2[tid] - mg2[tid] * s;
    }
    __syncthreads();
    for (int e = tid; e < 1024; e += 256) {
        int o = e >> 5, c = e & 31;
        sW1[o * 33 + c] = Wg1[e] * sS1[o];
        sW2[o * 33 + c] = Wg2[e] * sS2[o];
    }
    __syncthreads();

    int pt = blockIdx.x * 8 + w;
    int b = pt >> 12;
    int idxv = (lane < KNN) ? g_idx[pt * KNN + lane] : 0;
    if (lane < 4)
        *(float4*)&sCtr[w][lane * 4] = *(const float4*)&g_hb[(size_t)pt * C_BOT + lane * 4];
#pragma unroll
    for (int t = 0; t < 3; t++) {
        int e = lane + t * 32;
        int row = (e < 80) ? (e >> 2) : 0;
        int ni = __shfl_sync(0xffffffffu, idxv, row);
        if (e < 80) {
            int q = e & 3;
            float4 v = *(const float4*)&g_hb[((size_t)(b << 12) + ni) * C_BOT + q * 4];
            *(float4*)&sNb[w][row * 16 + q * 4] = v;
        }
    }
    __syncwarp();

    float ctr[16];
#pragma unroll
    for (int c = 0; c < 16; c++) ctr[c] = sCtr[w][c];

    float cd1 = t1[lane], cd2 = t2[lane];
#pragma unroll
    for (int c = 0; c < 16; c++) {
        cd1 += sW1[lane * 33 + 16 + c] * ctr[c];
        cd2 += sW2[lane * 33 + 16 + c] * ctr[c];
    }
    float m1 = -FLT_MAX, m2 = -FLT_MAX;
#pragma unroll
    for (int k = 0; k < KNN; k++) {
        float a = cd1;
#pragma unroll
        for (int c = 0; c < 16; c++) a += sW1[lane * 33 + c] * sNb[w][k * 16 + c];
        a = a > 0.f ? a : 0.2f * a;
        m1 = fmaxf(m1, a);
        if ((k & 1) == 0) {
            float a2 = cd2;
#pragma unroll
            for (int c = 0; c < 16; c++) a2 += sW2[lane * 33 + c] * sNb[w][k * 16 + c];
            a2 = a2 > 0.f ? a2 : 0.2f * a2;
            m2 = fmaxf(m2, a2);
        }
    }
    float gmx;
    if (lane < 16) {
        gmx = -FLT_MAX;
#pragma unroll
        for (int k = 0; k < KNN; k++) gmx = fmaxf(gmx, sNb[w][k * 16 + lane]);
    } else {
        gmx = ctr[lane - 16];
    }
    float* ap = g_allf + (size_t)pt * 96;
    ap[lane] = m1; ap[32 + lane] = m2; ap[64 + lane] = gmx;
}

// -------- K4c: decoder+residual GEMM, 128o x 64n tiles ----------------------
#define FPAD 68
__global__ void __launch_bounds__(256) k_dec(const float* __restrict__ x,
                                             float* __restrict__ out)
{
    extern __shared__ float sm[];
    float* sW = sm;
    float* sF = sW + 160 * 128;
    float* sB = sF + 16 * FPAD;

    int tid = threadIdx.x;
    int b = blockIdx.y, n0 = blockIdx.x * 64;
    size_t gr0 = (size_t)b * N_PTS + n0;

    for (int e = tid; e < 160 * 128 / 4; e += 256)
        ((float4*)sW)[e] = ((const float4*)g_Wt)[e];
    sB[tid] = g_bias[tid];
    __syncthreads();

    int to = tid & 31, tn = tid >> 5;
    float acc[4][8];
    float res[4][8];

#pragma unroll
    for (int i = 0; i < 4; i++)
#pragma unroll
        for (int j = 0; j < 8; j++) acc[i][j] = 0.f;

    for (int kc = 0; kc < 6; kc++) {
        {
            int row = tid >> 2, q = tid & 3;
            float4 v = *(const float4*)&g_allf[(gr0 + row) * 96 + kc * 16 + q * 4];
            sF[(q * 4 + 0) * FPAD + row] = v.x;
            sF[(q * 4 + 1) * FPAD + row] = v.y;
            sF[(q * 4 + 2) * FPAD + row] = v.z;
            sF[(q * 4 + 3) * FPAD + row] = v.w;
        }
        __syncthreads();
#pragma unroll
        for (int k = 0; k < 16; k++) {
            float4 wv = *(float4*)&sW[(kc * 16 + k) * 128 + to * 4];
            float4 f0 = *(float4*)&sF[k * FPAD + tn * 8];
            float4 f1 = *(float4*)&sF[k * FPAD + tn * 8 + 4];
            float wr[4] = {wv.x, wv.y, wv.z, wv.w};
            float fr[8] = {f0.x, f0.y, f0.z, f0.w, f1.x, f1.y, f1.z, f1.w};
#pragma unroll
            for (int i = 0; i < 4; i++)
#pragma unroll
                for (int j = 0; j < 8; j++) acc[i][j] += wr[i] * fr[j];
        }
        __syncthreads();
    }
#pragma unroll
    for (int i = 0; i < 4; i++) {
        float bv = sB[to * 4 + i];
#pragma unroll
        for (int j = 0; j < 8; j++) {
            res[i][j] = fmaxf(acc[i][j] + bv, 0.f);
            acc[i][j] = 0.f;
        }
    }

    for (int kc = 0; kc < 4; kc++) {
        {
            int c = tid >> 4, nq = tid & 15;
            float4 v = *(const float4*)&x[((size_t)(b * C_IN + kc * 16 + c)) * N_PTS +
                                          n0 + nq * 4];
            *(float4*)&sF[c * FPAD + nq * 4] = v;
        }
        __syncthreads();
#pragma unroll
        for (int k = 0; k < 16; k++) {
            float4 wv = *(float4*)&sW[(96 + kc * 16 + k) * 128 + to * 4];
            float4 f0 = *(float4*)&sF[k * FPAD + tn * 8];
            float4 f1 = *(float4*)&sF[k * FPAD + tn * 8 + 4];
            float wr[4] = {wv.x, wv.y, wv.z, wv.w};
            float fr[8] = {f0.x, f0.y, f0.z, f0.w, f1.x, f1.y, f1.z, f1.w};
#pragma unroll
            for (int i = 0; i < 4; i++)
#pragma unroll
                for (int j = 0; j < 8; j++) acc[i][j] += wr[i] * fr[j];
        }
        __syncthreads();
    }

#pragma unroll
    for (int i = 0; i < 4; i++) {
        int o = to * 4 + i;
        float bv = sB[128 + o];
        float4 r0, r1;
        r0.x = res[i][0] + fmaxf(acc[i][0] + bv, 0.f);
        r0.y = res[i][1] + fmaxf(acc[i][1] + bv, 0.f);
        r0.z = res[i][2] + fmaxf(acc[i][2] + bv, 0.f);
        r0.w = res[i][3] + fmaxf(acc[i][3] + bv, 0.f);
        r1.x = res[i][4] + fmaxf(acc[i][4] + bv, 0.f);
        r1.y = res[i][5] + fmaxf(acc[i][5] + bv, 0.f);
        r1.z = res[i][6] + fmaxf(acc[i][6] + bv, 0.f);
        r1.w = res[i][7] + fmaxf(acc[i][7] + bv, 0.f);
        float* op = out + ((size_t)(b * C_OUT + o)) * N_PTS + n0 + tn * 8;
        *(float4*)op = r0;
        *(float4*)(op + 4) = r1;
    }
}

// ---------------- launch -----------------------------------------------------
extern "C" void kernel_launch(void* const* d_in, const int* in_sizes, int n_in,
                              void* d_out, int out_size)
{
    const float* x    = (const float*)d_in[0];
    const float* Wres = (const float*)d_in[1];
    const float* gres = (const float*)d_in[2];
    const float* bres = (const float*)d_in[3];
    const float* mres = (const float*)d_in[4];
    const float* vres = (const float*)d_in[5];
    const float* Wbot = (const float*)d_in[6];
    const float* gbot = (const float*)d_in[7];
    const float* bbot = (const float*)d_in[8];
    const float* mbot = (const float*)d_in[9];
    const float* vbot = (const float*)d_in[10];
    const float* Wg1  = (const float*)d_in[11];
    const float* gg1  = (const float*)d_in[12];
    const float* bg1  = (const float*)d_in[13];
    const float* mg1  = (const float*)d_in[14];
    const float* vg1  = (const float*)d_in[15];
    const float* Wg2  = (const float*)d_in[16];
    const float* gg2  = (const float*)d_in[17];
    const float* bg2  = (const float*)d_in[18];
    const float* mg2  = (const float*)d_in[19];
    const float* vg2  = (const float*)d_in[20];
    const float* Wdec = (const float*)d_in[21];
    const float* gdec = (const float*)d_in[22];
    const float* bdec = (const float*)d_in[23];
    const float* mdec = (const float*)d_in[24];
    const float* vdec = (const float*)d_in[25];
    float* out = (float*)d_out;

    size_t smem_dist = SM_DIST_FLOATS * sizeof(float);
    cudaFuncSetAttribute(k_dist, cudaFuncAttributeMaxDynamicSharedMemorySize,
                         (int)smem_dist);
    size_t smem_dec = (160 * 128 + 16 * FPAD + 256) * sizeof(float);
    cudaFuncSetAttribute(k_dec, cudaFuncAttributeMaxDynamicSharedMemorySize,
                         (int)smem_dec);

    k_prep<<<65, 256>>>(x, Wbot, gbot, bbot, mbot, vbot,
                        Wdec, gdec, bdec, mdec, vdec,
                        Wres, gres, bres, mres, vres);
    k_dist<<<dim3(N_PTS / 128, N_PTS / 128, BATCH), 256, smem_dist>>>(x);
    k_topk<<<BATCH * N_PTS / 8, 256>>>();
    k_gcn<<<BATCH * N_PTS / 8, 256>>>(Wg1, gg1, bg1, mg1, vg1,
                                      Wg2, gg2, bg2, mg2, vg2);
    k_dec<<<dim3(N_PTS / 64, BATCH), 256, smem_dec>>>(x, out);
}